// round 11
// baseline (speedup 1.0000x reference)
#include <cuda_runtime.h>
#include <cuda_bf16.h>
#include <math_constants.h>
#include <cstdint>

#define T_SEQ 4096
#define H_DIM 2048
#define I_DIM 8192

// ---------------- scratch (device globals; no runtime allocation) ----------------
__device__ float g_x  [T_SEQ * H_DIM];       // LN output
__device__ float g_k  [T_SEQ * H_DIM];
__device__ float g_v  [T_SEQ * H_DIM];       // v, later kv
__device__ float g_r  [T_SEQ * H_DIM];       // sigmoid(r), later rr
// bf16 split activation buffers
__device__ __nv_bfloat16 g_Ah[(size_t)T_SEQ * H_DIM];  // kx / wkv / ffn-kx
__device__ __nv_bfloat16 g_Al[(size_t)T_SEQ * H_DIM];
__device__ __nv_bfloat16 g_Vh[(size_t)T_SEQ * H_DIM];  // vx
__device__ __nv_bfloat16 g_Vl[(size_t)T_SEQ * H_DIM];
__device__ __nv_bfloat16 g_Rh[(size_t)T_SEQ * H_DIM];  // rx / ffn-rx
__device__ __nv_bfloat16 g_Rl[(size_t)T_SEQ * H_DIM];
__device__ __nv_bfloat16 g_Kh[(size_t)T_SEQ * I_DIM];  // kk split (ffn inner)
__device__ __nv_bfloat16 g_Kl[(size_t)T_SEQ * I_DIM];
// weight split buffers (transposed, K-major)
__device__ __nv_bfloat16 g_Bh[(size_t)H_DIM * I_DIM];
__device__ __nv_bfloat16 g_Bl[(size_t)H_DIM * I_DIM];

// ---------------- helpers ----------------
__device__ __forceinline__ uint32_t smem_u32(const void* p) {
    uint32_t a;
    asm("{ .reg .u64 t; cvta.to.shared.u64 t, %1; cvt.u32.u64 %0, t; }" : "=r"(a) : "l"(p));
    return a;
}
#define SWZ128(o) ((o) ^ (((o) >> 3) & 0x70))

__device__ __forceinline__ void cp_async16(uint32_t dst, const void* src) {
    asm volatile("cp.async.cg.shared.global [%0], [%1], 16;" :: "r"(dst), "l"(src));
}
#define CP_COMMIT() asm volatile("cp.async.commit_group;" ::: "memory")

__device__ __forceinline__ void ldm_x4(uint32_t* r, uint32_t addr) {
    asm volatile("ldmatrix.sync.aligned.m8n8.x4.shared.b16 {%0,%1,%2,%3}, [%4];"
                 : "=r"(r[0]), "=r"(r[1]), "=r"(r[2]), "=r"(r[3]) : "r"(addr));
}
__device__ __forceinline__ void mma16816(float* c, const uint32_t* a, const uint32_t* b) {
    asm volatile(
        "mma.sync.aligned.m16n8k16.row.col.f32.bf16.bf16.f32 "
        "{%0,%1,%2,%3}, {%4,%5,%6,%7}, {%8,%9}, {%0,%1,%2,%3};"
        : "+f"(c[0]), "+f"(c[1]), "+f"(c[2]), "+f"(c[3])
        : "r"(a[0]), "r"(a[1]), "r"(a[2]), "r"(a[3]), "r"(b[0]), "r"(b[1]));
}
__device__ __forceinline__ void split_bf16(float v, __nv_bfloat16& h, __nv_bfloat16& l) {
    h = __float2bfloat16(v);
    l = __float2bfloat16(v - __bfloat162float(h));
}

// ---------------- mma.sync GEMM v2: C[M,N] = A[M,K] @ B[N,K]^T  (3-term bf16 split) ----
// BM=128, BN=256, BK=64, 512 threads (16 warps, 4Mx4N, warp tile 32x64).
// Per k-chunk: load {Ah,Al,Bh,Bl} ONCE (96KB stage, 2 stages), then 3 MMA passes
// (AhBh, AlBh, AhBl) from the same smem -> 1/3 the global traffic, 3x HMMA per barrier.
// EPI: 0=none 1=sigmoid 2=relu^2(fp32) 3=+=res 4=relu^2 -> bf16 hi/lo split
#define STAGE_BYTES 98304
template <int EPI>
__global__ __launch_bounds__(512) void mma_gemm(const __nv_bfloat16* __restrict__ Ah,
                                                const __nv_bfloat16* __restrict__ Al,
                                                const __nv_bfloat16* __restrict__ Bh,
                                                const __nv_bfloat16* __restrict__ Bl,
                                                float* __restrict__ C,
                                                const float* __restrict__ res,
                                                __nv_bfloat16* __restrict__ Chi,
                                                __nv_bfloat16* __restrict__ Clo,
                                                int M, int N, int K) {
    extern __shared__ char dsm[];
    char* smem = (char*)(((uintptr_t)dsm + 1023u) & ~(uintptr_t)1023u);
    const uint32_t sbase = smem_u32(smem);

    const int tid = threadIdx.x;
    const int wid = tid >> 5, lane = tid & 31;
    const int warp_m = wid & 3;        // 4 warps along M (32 rows each)
    const int warp_n = wid >> 2;       // 4 warps along N (64 cols each)
    const int bm = blockIdx.y * 128, bn = blockIdx.x * 256;

    const int KC = K >> 6;             // 64-wide K chunks

    // ldmatrix per-lane coordinates
    const int a_row = (lane & 15);
    const int a_kb  = (lane >> 4) * 16;
    const int b_row = (lane & 7) + ((lane >> 4) << 3);
    const int b_kb  = ((lane >> 3) & 1) * 16;

    float acc[2][8][4];
#pragma unroll
    for (int i = 0; i < 2; i++)
#pragma unroll
        for (int j = 0; j < 8; j++)
#pragma unroll
            for (int q = 0; q < 4; q++) acc[i][j][q] = 0.f;

    // load chunk c (all 4 tiles) into stage p
    auto issue = [&](int c, int p) {
        const int k0 = c << 6;
        const uint32_t st = sbase + p * STAGE_BYTES;
        // A tiles: 128 rows x 128B, 1024 transfers -> 2 per thread per tile
#pragma unroll
        for (int j = 0; j < 2; j++) {
            const int i = tid + 512 * j;
            const int row = i >> 3, seg = i & 7;
            const uint32_t off = SWZ128((uint32_t)(row * 128 + seg * 16));
            const size_t g = (size_t)(bm + row) * K + k0 + seg * 8;
            cp_async16(st + off,         Ah + g);
            cp_async16(st + 16384 + off, Al + g);
        }
        // B tiles: 256 rows x 128B, 2048 transfers -> 4 per thread per tile
#pragma unroll
        for (int j = 0; j < 4; j++) {
            const int i = tid + 512 * j;
            const int row = i >> 3, seg = i & 7;
            const uint32_t off = SWZ128((uint32_t)(row * 128 + seg * 16));
            const size_t g = (size_t)(bn + row) * K + k0 + seg * 8;
            cp_async16(st + 32768 + off, Bh + g);
            cp_async16(st + 65536 + off, Bl + g);
        }
        CP_COMMIT();
    };

    issue(0, 0);

    for (int c = 0; c < KC; c++) {
        if (c + 1 < KC) {
            issue(c + 1, (c + 1) & 1);
            asm volatile("cp.async.wait_group 1;" ::: "memory");
        } else {
            asm volatile("cp.async.wait_group 0;" ::: "memory");
        }
        __syncthreads();

        const uint32_t st = sbase + (c & 1) * STAGE_BYTES;
        // 3 passes from the same stage: (Ah,Bh), (Al,Bh), (Ah,Bl)
#pragma unroll
        for (int pass = 0; pass < 3; pass++) {
            const uint32_t abuf = st + ((pass == 1) ? 16384u : 0u);
            const uint32_t bbuf = st + 32768u + ((pass == 2) ? 32768u : 0u);
#pragma unroll
            for (int ks = 0; ks < 4; ks++) {
                uint32_t afr[2][4];
#pragma unroll
                for (int mt = 0; mt < 2; mt++) {
                    const uint32_t off = (uint32_t)((warp_m * 32 + mt * 16 + a_row) * 128 + ks * 32 + a_kb);
                    ldm_x4(afr[mt], abuf + SWZ128(off));
                }
                uint32_t bfr[8][2];
#pragma unroll
                for (int np = 0; np < 4; np++) {
                    uint32_t r[4];
                    const uint32_t off = (uint32_t)((warp_n * 64 + np * 16 + b_row) * 128 + ks * 32 + b_kb);
                    ldm_x4(r, bbuf + SWZ128(off));
                    bfr[2 * np][0] = r[0];  bfr[2 * np][1] = r[1];
                    bfr[2 * np + 1][0] = r[2];  bfr[2 * np + 1][1] = r[3];
                }
#pragma unroll
                for (int mt = 0; mt < 2; mt++)
#pragma unroll
                    for (int nt = 0; nt < 8; nt++)
                        mma16816(acc[mt][nt], afr[mt], bfr[nt]);
            }
        }
        __syncthreads();
    }

    // ---- epilogue ----
    const int trow = lane >> 2;
    const int tcol = (lane & 3) * 2;
#pragma unroll
    for (int mt = 0; mt < 2; mt++) {
#pragma unroll
        for (int nt = 0; nt < 8; nt++) {
            const int row0 = bm + warp_m * 32 + mt * 16 + trow;
            const int col  = bn + warp_n * 64 + nt * 8 + tcol;
#pragma unroll
            for (int h = 0; h < 2; h++) {
                const int row = row0 + h * 8;
                float v0 = acc[mt][nt][2 * h + 0];
                float v1 = acc[mt][nt][2 * h + 1];
                const size_t base = (size_t)row * N + col;
                if (EPI == 1) {
                    v0 = 1.f / (1.f + __expf(-v0));
                    v1 = 1.f / (1.f + __expf(-v1));
                } else if (EPI == 2 || EPI == 4) {
                    v0 = fmaxf(v0, 0.f); v0 *= v0;
                    v1 = fmaxf(v1, 0.f); v1 *= v1;
                } else if (EPI == 3) {
                    const float2 rv = *reinterpret_cast<const float2*>(&res[base]);
                    v0 += rv.x; v1 += rv.y;
                }
                if (EPI == 4) {
                    __nv_bfloat16 h0, l0, h1, l1;
                    split_bf16(v0, h0, l0);
                    split_bf16(v1, h1, l1);
                    *reinterpret_cast<__nv_bfloat162*>(&Chi[base]) = __nv_bfloat162(h0, h1);
                    *reinterpret_cast<__nv_bfloat162*>(&Clo[base]) = __nv_bfloat162(l0, l1);
                } else {
                    *reinterpret_cast<float2*>(&C[base]) = make_float2(v0, v1);
                }
            }
        }
    }
}

// ---------------- weight transpose + split: W[K,N] fp32 -> [N,K] bf16 hi/lo ----------------
__global__ __launch_bounds__(256) void convert_wt(const float* __restrict__ W,
                                                  __nv_bfloat16* __restrict__ Th,
                                                  __nv_bfloat16* __restrict__ Tl,
                                                  int K, int N) {
    __shared__ float tile[32][33];
    const int tx = threadIdx.x & 31, ty = threadIdx.x >> 5;
    const int k0 = blockIdx.y * 32, n0 = blockIdx.x * 32;
#pragma unroll
    for (int j = 0; j < 4; j++)
        tile[ty + j * 8][tx] = W[(size_t)(k0 + ty + j * 8) * N + n0 + tx];
    __syncthreads();
#pragma unroll
    for (int j = 0; j < 4; j++) {
        const float v = tile[tx][ty + j * 8];
        __nv_bfloat16 h, l;
        split_bf16(v, h, l);
        const size_t o = (size_t)(n0 + ty + j * 8) * K + k0 + tx;
        Th[o] = h;
        Tl[o] = l;
    }
}

// ---------------- LayerNorm ----------------
__global__ __launch_bounds__(256) void ln_kernel(const float* __restrict__ in,
                                                 const float* __restrict__ sc,
                                                 const float* __restrict__ bi,
                                                 float* __restrict__ out) {
    __shared__ float red0[8], red1[8];
    const int t = blockIdx.x;
    const float* row = in + (size_t)t * H_DIM;
    float v[8];
    float s = 0.f, ss = 0.f;
#pragma unroll
    for (int i = 0; i < 8; i++) {
        v[i] = row[threadIdx.x + i * 256];
        s += v[i]; ss += v[i] * v[i];
    }
#pragma unroll
    for (int o = 16; o; o >>= 1) {
        s  += __shfl_xor_sync(0xffffffffu, s, o);
        ss += __shfl_xor_sync(0xffffffffu, ss, o);
    }
    const int w = threadIdx.x >> 5, l = threadIdx.x & 31;
    if (l == 0) { red0[w] = s; red1[w] = ss; }
    __syncthreads();
    if (threadIdx.x < 32) {
        s  = (l < 8) ? red0[l] : 0.f;
        ss = (l < 8) ? red1[l] : 0.f;
#pragma unroll
        for (int o = 4; o; o >>= 1) {
            s  += __shfl_xor_sync(0xffffffffu, s, o);
            ss += __shfl_xor_sync(0xffffffffu, ss, o);
        }
        if (l == 0) { red0[0] = s; red1[0] = ss; }
    }
    __syncthreads();
    const float mean = red0[0] * (1.f / H_DIM);
    const float var  = red1[0] * (1.f / H_DIM) - mean * mean;
    const float inv  = rsqrtf(var + 1e-5f);
    float* orow = out + (size_t)t * H_DIM;
#pragma unroll
    for (int i = 0; i < 8; i++) {
        const int h = threadIdx.x + i * 256;
        orow[h] = (v[i] - mean) * inv * sc[h] + bi[h];
    }
}

// ---------------- token-shift mixes, fused bf16 split output ----------------
__global__ __launch_bounds__(256) void mix3_kernel(const float* __restrict__ x,
                                                   const float* __restrict__ tmk,
                                                   const float* __restrict__ tmv,
                                                   const float* __restrict__ tmr,
                                                   __nv_bfloat16* __restrict__ kxh, __nv_bfloat16* __restrict__ kxl,
                                                   __nv_bfloat16* __restrict__ vxh, __nv_bfloat16* __restrict__ vxl,
                                                   __nv_bfloat16* __restrict__ rxh, __nv_bfloat16* __restrict__ rxl) {
    const int idx = blockIdx.x * 256 + threadIdx.x;
    const int h = idx & (H_DIM - 1);
    const float xv = x[idx];
    const float cx = (idx >= H_DIM) ? x[idx - H_DIM] : 0.f;
    const float a = tmk[h], b = tmv[h], c = tmr[h];
    __nv_bfloat16 hh, ll;
    split_bf16(xv * a + cx * (1.f - a), hh, ll);  kxh[idx] = hh; kxl[idx] = ll;
    split_bf16(xv * b + cx * (1.f - b), hh, ll);  vxh[idx] = hh; vxl[idx] = ll;
    split_bf16(xv * c + cx * (1.f - c), hh, ll);  rxh[idx] = hh; rxl[idx] = ll;
}

__global__ __launch_bounds__(256) void mix2_kernel(const float* __restrict__ x,
                                                   const float* __restrict__ tmk,
                                                   const float* __restrict__ tmr,
                                                   __nv_bfloat16* __restrict__ kxh, __nv_bfloat16* __restrict__ kxl,
                                                   __nv_bfloat16* __restrict__ rxh, __nv_bfloat16* __restrict__ rxl) {
    const int idx = blockIdx.x * 256 + threadIdx.x;
    const int h = idx & (H_DIM - 1);
    const float xv = x[idx];
    const float cx = (idx >= H_DIM) ? x[idx - H_DIM] : 0.f;
    const float a = tmk[h], c = tmr[h];
    __nv_bfloat16 hh, ll;
    split_bf16(xv * a + cx * (1.f - a), hh, ll);  kxh[idx] = hh; kxl[idx] = ll;
    split_bf16(xv * c + cx * (1.f - c), hh, ll);  rxh[idx] = hh; rxl[idx] = ll;
}

// ---------------- WKV serial scan with group-of-16 register prefetch ----------------
#define WKV_G 16
__global__ __launch_bounds__(256) void wkv_kernel(const float* __restrict__ k,
                                                  const float* __restrict__ v,
                                                  const float* __restrict__ r,
                                                  const float* __restrict__ time_first,
                                                  const float* __restrict__ time_decay,
                                                  __nv_bfloat16* __restrict__ outh,
                                                  __nv_bfloat16* __restrict__ outl) {
    const int h = blockIdx.x * 256 + threadIdx.x;
    const float u = time_first[h];
    const float w = -__expf(time_decay[h]);
    float aa = 0.f, bb = 0.f, pp = -CUDART_INF_F;

    float kb[WKV_G], vb[WKV_G], rb[WKV_G];
    for (int t0 = 0; t0 < T_SEQ; t0 += WKV_G) {
        const size_t base0 = (size_t)t0 * H_DIM + h;
#pragma unroll
        for (int j = 0; j < WKV_G; j++) {
            const size_t idx = base0 + (size_t)j * H_DIM;
            kb[j] = __ldg(&k[idx]);
            vb[j] = __ldg(&v[idx]);
            rb[j] = __ldg(&r[idx]);
        }
#pragma unroll
        for (int j = 0; j < WKV_G; j++) {
            const float kk = kb[j];
            const float vv = vb[j];
            const float ww = u + kk;
            const float p  = fmaxf(pp, ww);
            const float e1 = __expf(pp - p);
            const float e2 = __expf(ww - p);
            const float o  = rb[j] * __fdividef(e1 * aa + e2 * vv, e1 * bb + e2);
            __nv_bfloat16 hh, ll;
            split_bf16(o, hh, ll);
            const size_t idx = base0 + (size_t)j * H_DIM;
            outh[idx] = hh; outl[idx] = ll;
            const float ww2 = w + pp;
            const float p2  = fmaxf(ww2, kk);
            const float e1b = __expf(ww2 - p2);
            const float e2b = __expf(kk - p2);
            aa = e1b * aa + e2b * vv;
            bb = e1b * bb + e2b;
            pp = p2;
        }
    }
}

__global__ __launch_bounds__(256) void gate_add_kernel(float* __restrict__ out,
                                                       const float* __restrict__ rr,
                                                       const float* __restrict__ kv) {
    const int idx = blockIdx.x * 256 + threadIdx.x;
    out[idx] += rr[idx] * kv[idx];
}

// ---------------- launch ----------------
extern "C" void kernel_launch(void* const* d_in, const int* in_sizes, int n_in,
                              void* d_out, int out_size) {
    const float* hidden     = (const float*)d_in[0];
    const float* ln1_scale  = (const float*)d_in[1];
    const float* ln1_bias   = (const float*)d_in[2];
    const float* ln2_scale  = (const float*)d_in[3];
    const float* ln2_bias   = (const float*)d_in[4];
    const float* time_decay = (const float*)d_in[5];
    const float* time_first = (const float*)d_in[6];
    const float* tm_k       = (const float*)d_in[7];
    const float* tm_v       = (const float*)d_in[8];
    const float* tm_r       = (const float*)d_in[9];
    const float* Wk         = (const float*)d_in[10];
    const float* Wv         = (const float*)d_in[11];
    const float* Wr         = (const float*)d_in[12];
    const float* Wo         = (const float*)d_in[13];
    const float* ffn_tm_k   = (const float*)d_in[14];
    const float* ffn_tm_r   = (const float*)d_in[15];
    const float* Wk_ff      = (const float*)d_in[16];
    const float* Wv_ff      = (const float*)d_in[17];
    const float* Wr_ff      = (const float*)d_in[18];
    float* out = (float*)d_out;

    float *x, *k, *v, *r;
    __nv_bfloat16 *Ah, *Al, *Vh, *Vl, *Rh, *Rl, *Kh, *Kl, *Bh, *Bl;
    cudaGetSymbolAddress((void**)&x,  g_x);
    cudaGetSymbolAddress((void**)&k,  g_k);
    cudaGetSymbolAddress((void**)&v,  g_v);
    cudaGetSymbolAddress((void**)&r,  g_r);
    cudaGetSymbolAddress((void**)&Ah, g_Ah);
    cudaGetSymbolAddress((void**)&Al, g_Al);
    cudaGetSymbolAddress((void**)&Vh, g_Vh);
    cudaGetSymbolAddress((void**)&Vl, g_Vl);
    cudaGetSymbolAddress((void**)&Rh, g_Rh);
    cudaGetSymbolAddress((void**)&Rl, g_Rl);
    cudaGetSymbolAddress((void**)&Kh, g_Kh);
    cudaGetSymbolAddress((void**)&Kl, g_Kl);
    cudaGetSymbolAddress((void**)&Bh, g_Bh);
    cudaGetSymbolAddress((void**)&Bl, g_Bl);

    static const int SMEM_BYTES = 2 * STAGE_BYTES + 1024;   // 197632
    cudaFuncSetAttribute(mma_gemm<0>, cudaFuncAttributeMaxDynamicSharedMemorySize, SMEM_BYTES);
    cudaFuncSetAttribute(mma_gemm<1>, cudaFuncAttributeMaxDynamicSharedMemorySize, SMEM_BYTES);
    cudaFuncSetAttribute(mma_gemm<3>, cudaFuncAttributeMaxDynamicSharedMemorySize, SMEM_BYTES);
    cudaFuncSetAttribute(mma_gemm<4>, cudaFuncAttributeMaxDynamicSharedMemorySize, SMEM_BYTES);

    const int ebH = (T_SEQ * H_DIM) / 256;
    const dim3 gHH(H_DIM / 256, T_SEQ / 128);   // N=2048 -> (8, 32)
    const dim3 gHI(I_DIM / 256, T_SEQ / 128);   // N=8192 -> (32, 32)
    const dim3 wtHH(H_DIM / 32, H_DIM / 32);
    const dim3 wtHI(I_DIM / 32, H_DIM / 32);
    const dim3 wtIH(H_DIM / 32, I_DIM / 32);

    // ---- time-mix ----
    ln_kernel<<<T_SEQ, 256>>>(hidden, ln1_scale, ln1_bias, x);
    mix3_kernel<<<ebH, 256>>>(x, tm_k, tm_v, tm_r, Ah, Al, Vh, Vl, Rh, Rl);

    convert_wt<<<wtHH, 256>>>(Wr, Bh, Bl, H_DIM, H_DIM);
    mma_gemm<1><<<gHH, 512, SMEM_BYTES>>>(Rh, Rl, Bh, Bl, r, nullptr, nullptr, nullptr, T_SEQ, H_DIM, H_DIM);

    convert_wt<<<wtHH, 256>>>(Wk, Bh, Bl, H_DIM, H_DIM);
    mma_gemm<0><<<gHH, 512, SMEM_BYTES>>>(Ah, Al, Bh, Bl, k, nullptr, nullptr, nullptr, T_SEQ, H_DIM, H_DIM);

    convert_wt<<<wtHH, 256>>>(Wv, Bh, Bl, H_DIM, H_DIM);
    mma_gemm<0><<<gHH, 512, SMEM_BYTES>>>(Vh, Vl, Bh, Bl, v, nullptr, nullptr, nullptr, T_SEQ, H_DIM, H_DIM);

    wkv_kernel<<<H_DIM / 256, 256>>>(k, v, r, time_first, time_decay, Ah, Al);  // r*wkv -> Ah/Al

    convert_wt<<<wtHH, 256>>>(Wo, Bh, Bl, H_DIM, H_DIM);
    mma_gemm<3><<<gHH, 512, SMEM_BYTES>>>(Ah, Al, Bh, Bl, out, hidden, nullptr, nullptr, T_SEQ, H_DIM, H_DIM);

    // ---- channel-mix ----
    ln_kernel<<<T_SEQ, 256>>>(out, ln2_scale, ln2_bias, x);
    mix2_kernel<<<ebH, 256>>>(x, ffn_tm_k, ffn_tm_r, Ah, Al, Rh, Rl);

    convert_wt<<<wtHH, 256>>>(Wr_ff, Bh, Bl, H_DIM, H_DIM);
    mma_gemm<1><<<gHH, 512, SMEM_BYTES>>>(Rh, Rl, Bh, Bl, r, nullptr, nullptr, nullptr, T_SEQ, H_DIM, H_DIM);

    convert_wt<<<wtHI, 256>>>(Wk_ff, Bh, Bl, H_DIM, I_DIM);
    mma_gemm<4><<<gHI, 512, SMEM_BYTES>>>(Ah, Al, Bh, Bl, nullptr, nullptr, Kh, Kl, T_SEQ, I_DIM, H_DIM);

    convert_wt<<<wtIH, 256>>>(Wv_ff, Bh, Bl, I_DIM, H_DIM);
    mma_gemm<0><<<gHH, 512, SMEM_BYTES>>>(Kh, Kl, Bh, Bl, v, nullptr, nullptr, nullptr, T_SEQ, H_DIM, I_DIM);

    gate_add_kernel<<<ebH, 256>>>(out, r, v);
}

// round 12
// speedup vs baseline: 1.1431x; 1.1431x over previous
#include <cuda_runtime.h>
#include <cuda_bf16.h>
#include <math_constants.h>
#include <cstdint>

#define T_SEQ 4096
#define H_DIM 2048
#define I_DIM 8192

// ---------------- scratch (device globals; no runtime allocation) ----------------
__device__ float g_x  [T_SEQ * H_DIM];       // LN output
__device__ float g_k  [T_SEQ * H_DIM];
__device__ float g_v  [T_SEQ * H_DIM];       // v, later kv
__device__ float g_r  [T_SEQ * H_DIM];       // sigmoid(r), later rr
// bf16 split activation buffers
__device__ __nv_bfloat16 g_Ah[(size_t)T_SEQ * H_DIM];  // kx / wkv / ffn-kx
__device__ __nv_bfloat16 g_Al[(size_t)T_SEQ * H_DIM];
__device__ __nv_bfloat16 g_Vh[(size_t)T_SEQ * H_DIM];  // vx
__device__ __nv_bfloat16 g_Vl[(size_t)T_SEQ * H_DIM];
__device__ __nv_bfloat16 g_Rh[(size_t)T_SEQ * H_DIM];  // rx / ffn-rx
__device__ __nv_bfloat16 g_Rl[(size_t)T_SEQ * H_DIM];
__device__ __nv_bfloat16 g_Kh[(size_t)T_SEQ * I_DIM];  // kk split (ffn inner)
__device__ __nv_bfloat16 g_Kl[(size_t)T_SEQ * I_DIM];
// weight split buffers (transposed, K-major)
__device__ __nv_bfloat16 g_Bh[(size_t)H_DIM * I_DIM];
__device__ __nv_bfloat16 g_Bl[(size_t)H_DIM * I_DIM];

// ---------------- helpers ----------------
__device__ __forceinline__ uint32_t smem_u32(const void* p) {
    uint32_t a;
    asm("{ .reg .u64 t; cvta.to.shared.u64 t, %1; cvt.u32.u64 %0, t; }" : "=r"(a) : "l"(p));
    return a;
}
#define SWZ128(o) ((o) ^ (((o) >> 3) & 0x70))

__device__ __forceinline__ void cp_async16(uint32_t dst, const void* src) {
    asm volatile("cp.async.cg.shared.global [%0], [%1], 16;" :: "r"(dst), "l"(src));
}
#define CP_COMMIT() asm volatile("cp.async.commit_group;" ::: "memory")

__device__ __forceinline__ void ldm_x4(uint32_t* r, uint32_t addr) {
    asm volatile("ldmatrix.sync.aligned.m8n8.x4.shared.b16 {%0,%1,%2,%3}, [%4];"
                 : "=r"(r[0]), "=r"(r[1]), "=r"(r[2]), "=r"(r[3]) : "r"(addr));
}
__device__ __forceinline__ void mma16816(float* c, const uint32_t* a, const uint32_t* b) {
    asm volatile(
        "mma.sync.aligned.m16n8k16.row.col.f32.bf16.bf16.f32 "
        "{%0,%1,%2,%3}, {%4,%5,%6,%7}, {%8,%9}, {%0,%1,%2,%3};"
        : "+f"(c[0]), "+f"(c[1]), "+f"(c[2]), "+f"(c[3])
        : "r"(a[0]), "r"(a[1]), "r"(a[2]), "r"(a[3]), "r"(b[0]), "r"(b[1]));
}
__device__ __forceinline__ void split_bf16(float v, __nv_bfloat16& h, __nv_bfloat16& l) {
    h = __float2bfloat16(v);
    l = __float2bfloat16(v - __bfloat162float(h));
}

// ---------------- mma.sync GEMM v3: C[M,N] = A[M,K] @ B[N,K]^T  (3-term bf16 split) ----
// BM=128, BN=128, BK=32, 256 threads (8 warps, 4Mx2N, warp tile 32x64).
// Packed stage rows: 128B row = [hi 32 cols | lo 32 cols] for A and for B.
// Stage = 32KB (A 16KB + B 16KB), 3 stages = 96KB/CTA -> 2 CTAs/SM preserved.
// Per chunk: 3 MMA passes (AhBh, AlBh, AhBl) from the SAME stage -> 1/3 traffic of R10.
// EPI: 0=none 1=sigmoid 2=relu^2(fp32) 3=+=res 4=relu^2 -> bf16 hi/lo split
#define STAGE_BYTES 32768
template <int EPI>
__global__ __launch_bounds__(256) void mma_gemm(const __nv_bfloat16* __restrict__ Ah,
                                                const __nv_bfloat16* __restrict__ Al,
                                                const __nv_bfloat16* __restrict__ Bh,
                                                const __nv_bfloat16* __restrict__ Bl,
                                                float* __restrict__ C,
                                                const float* __restrict__ res,
                                                __nv_bfloat16* __restrict__ Chi,
                                                __nv_bfloat16* __restrict__ Clo,
                                                int M, int N, int K) {
    extern __shared__ char dsm[];
    char* smem = (char*)(((uintptr_t)dsm + 1023u) & ~(uintptr_t)1023u);
    const uint32_t sbase = smem_u32(smem);

    const int tid = threadIdx.x;
    const int wid = tid >> 5, lane = tid & 31;
    const int warp_m = wid & 3;        // 4 warps along M (32 rows each)
    const int warp_n = wid >> 2;       // 2 warps along N (64 cols each)
    const int bm = blockIdx.y * 128, bn = blockIdx.x * 128;

    const int KC = K >> 5;             // 32-wide K chunks

    // ldmatrix per-lane coordinates
    const int a_row = (lane & 15);
    const int a_kb  = (lane >> 4) * 16;
    const int b_row = (lane & 7) + ((lane >> 4) << 3);
    const int b_kb  = ((lane >> 3) & 1) * 16;

    float acc[2][8][4];
#pragma unroll
    for (int i = 0; i < 2; i++)
#pragma unroll
        for (int j = 0; j < 8; j++)
#pragma unroll
            for (int q = 0; q < 4; q++) acc[i][j][q] = 0.f;

    // load chunk c (hi|lo packed rows for A and B) into stage p
    auto issue = [&](int c, int p) {
        const int k0 = c << 5;
        const uint32_t st = sbase + p * STAGE_BYTES;
#pragma unroll
        for (int j = 0; j < 4; j++) {
            const int i = tid + 256 * j;          // 0..1023
            const int row = i >> 3, seg = i & 7;  // 128 rows x 8 16B-segs
            const uint32_t off = SWZ128((uint32_t)(row * 128 + seg * 16));
            const int s4 = seg & 3;               // col segment within 32-col half
            const __nv_bfloat16* As = (seg < 4) ? Ah : Al;
            const __nv_bfloat16* Bs = (seg < 4) ? Bh : Bl;
            cp_async16(st + off,          As + (size_t)(bm + row) * K + k0 + s4 * 8);
            cp_async16(st + 16384 + off,  Bs + (size_t)(bn + row) * K + k0 + s4 * 8);
        }
        CP_COMMIT();
    };

    issue(0, 0);
    issue(1, 1);

    for (int c = 0; c < KC; c++) {
        if (c + 1 < KC) {
            asm volatile("cp.async.wait_group 1;" ::: "memory");
        } else {
            asm volatile("cp.async.wait_group 0;" ::: "memory");
        }
        __syncthreads();
        if (c + 2 < KC) issue(c + 2, (c + 2) % 3);

        const uint32_t st = sbase + (c % 3) * STAGE_BYTES;
        // 3 passes from the same stage: (Ah,Bh), (Al,Bh), (Ah,Bl)
#pragma unroll
        for (int pass = 0; pass < 3; pass++) {
            const uint32_t aofs = (pass == 1) ? 64u : 0u;   // lo half of A rows
            const uint32_t bofs = (pass == 2) ? 64u : 0u;   // lo half of B rows
#pragma unroll
            for (int ks = 0; ks < 2; ks++) {
                uint32_t afr[2][4];
#pragma unroll
                for (int mt = 0; mt < 2; mt++) {
                    const uint32_t off = (uint32_t)((warp_m * 32 + mt * 16 + a_row) * 128) + aofs + ks * 32 + a_kb;
                    ldm_x4(afr[mt], st + SWZ128(off));
                }
                uint32_t bfr[8][2];
#pragma unroll
                for (int np = 0; np < 4; np++) {
                    uint32_t r[4];
                    const uint32_t off = (uint32_t)((warp_n * 64 + np * 16 + b_row) * 128) + bofs + ks * 32 + b_kb;
                    ldm_x4(r, st + 16384u + SWZ128(off));
                    bfr[2 * np][0] = r[0];  bfr[2 * np][1] = r[1];
                    bfr[2 * np + 1][0] = r[2];  bfr[2 * np + 1][1] = r[3];
                }
#pragma unroll
                for (int mt = 0; mt < 2; mt++)
#pragma unroll
                    for (int nt = 0; nt < 8; nt++)
                        mma16816(acc[mt][nt], afr[mt], bfr[nt]);
            }
        }
        __syncthreads();
    }

    // ---- epilogue ----
    const int trow = lane >> 2;
    const int tcol = (lane & 3) * 2;
#pragma unroll
    for (int mt = 0; mt < 2; mt++) {
#pragma unroll
        for (int nt = 0; nt < 8; nt++) {
            const int row0 = bm + warp_m * 32 + mt * 16 + trow;
            const int col  = bn + warp_n * 64 + nt * 8 + tcol;
#pragma unroll
            for (int h = 0; h < 2; h++) {
                const int row = row0 + h * 8;
                float v0 = acc[mt][nt][2 * h + 0];
                float v1 = acc[mt][nt][2 * h + 1];
                const size_t base = (size_t)row * N + col;
                if (EPI == 1) {
                    v0 = 1.f / (1.f + __expf(-v0));
                    v1 = 1.f / (1.f + __expf(-v1));
                } else if (EPI == 2 || EPI == 4) {
                    v0 = fmaxf(v0, 0.f); v0 *= v0;
                    v1 = fmaxf(v1, 0.f); v1 *= v1;
                } else if (EPI == 3) {
                    const float2 rv = *reinterpret_cast<const float2*>(&res[base]);
                    v0 += rv.x; v1 += rv.y;
                }
                if (EPI == 4) {
                    __nv_bfloat16 h0, l0, h1, l1;
                    split_bf16(v0, h0, l0);
                    split_bf16(v1, h1, l1);
                    *reinterpret_cast<__nv_bfloat162*>(&Chi[base]) = __nv_bfloat162(h0, h1);
                    *reinterpret_cast<__nv_bfloat162*>(&Clo[base]) = __nv_bfloat162(l0, l1);
                } else {
                    *reinterpret_cast<float2*>(&C[base]) = make_float2(v0, v1);
                }
            }
        }
    }
}

// ---------------- weight transpose + split: W[K,N] fp32 -> [N,K] bf16 hi/lo ----------------
__global__ __launch_bounds__(256) void convert_wt(const float* __restrict__ W,
                                                  __nv_bfloat16* __restrict__ Th,
                                                  __nv_bfloat16* __restrict__ Tl,
                                                  int K, int N) {
    __shared__ float tile[32][33];
    const int tx = threadIdx.x & 31, ty = threadIdx.x >> 5;
    const int k0 = blockIdx.y * 32, n0 = blockIdx.x * 32;
#pragma unroll
    for (int j = 0; j < 4; j++)
        tile[ty + j * 8][tx] = W[(size_t)(k0 + ty + j * 8) * N + n0 + tx];
    __syncthreads();
#pragma unroll
    for (int j = 0; j < 4; j++) {
        const float v = tile[tx][ty + j * 8];
        __nv_bfloat16 h, l;
        split_bf16(v, h, l);
        const size_t o = (size_t)(n0 + ty + j * 8) * K + k0 + tx;
        Th[o] = h;
        Tl[o] = l;
    }
}

// ---------------- LayerNorm ----------------
__global__ __launch_bounds__(256) void ln_kernel(const float* __restrict__ in,
                                                 const float* __restrict__ sc,
                                                 const float* __restrict__ bi,
                                                 float* __restrict__ out) {
    __shared__ float red0[8], red1[8];
    const int t = blockIdx.x;
    const float* row = in + (size_t)t * H_DIM;
    float v[8];
    float s = 0.f, ss = 0.f;
#pragma unroll
    for (int i = 0; i < 8; i++) {
        v[i] = row[threadIdx.x + i * 256];
        s += v[i]; ss += v[i] * v[i];
    }
#pragma unroll
    for (int o = 16; o; o >>= 1) {
        s  += __shfl_xor_sync(0xffffffffu, s, o);
        ss += __shfl_xor_sync(0xffffffffu, ss, o);
    }
    const int w = threadIdx.x >> 5, l = threadIdx.x & 31;
    if (l == 0) { red0[w] = s; red1[w] = ss; }
    __syncthreads();
    if (threadIdx.x < 32) {
        s  = (l < 8) ? red0[l] : 0.f;
        ss = (l < 8) ? red1[l] : 0.f;
#pragma unroll
        for (int o = 4; o; o >>= 1) {
            s  += __shfl_xor_sync(0xffffffffu, s, o);
            ss += __shfl_xor_sync(0xffffffffu, ss, o);
        }
        if (l == 0) { red0[0] = s; red1[0] = ss; }
    }
    __syncthreads();
    const float mean = red0[0] * (1.f / H_DIM);
    const float var  = red1[0] * (1.f / H_DIM) - mean * mean;
    const float inv  = rsqrtf(var + 1e-5f);
    float* orow = out + (size_t)t * H_DIM;
#pragma unroll
    for (int i = 0; i < 8; i++) {
        const int h = threadIdx.x + i * 256;
        orow[h] = (v[i] - mean) * inv * sc[h] + bi[h];
    }
}

// ---------------- token-shift mixes, fused bf16 split output ----------------
__global__ __launch_bounds__(256) void mix3_kernel(const float* __restrict__ x,
                                                   const float* __restrict__ tmk,
                                                   const float* __restrict__ tmv,
                                                   const float* __restrict__ tmr,
                                                   __nv_bfloat16* __restrict__ kxh, __nv_bfloat16* __restrict__ kxl,
                                                   __nv_bfloat16* __restrict__ vxh, __nv_bfloat16* __restrict__ vxl,
                                                   __nv_bfloat16* __restrict__ rxh, __nv_bfloat16* __restrict__ rxl) {
    const int idx = blockIdx.x * 256 + threadIdx.x;
    const int h = idx & (H_DIM - 1);
    const float xv = x[idx];
    const float cx = (idx >= H_DIM) ? x[idx - H_DIM] : 0.f;
    const float a = tmk[h], b = tmv[h], c = tmr[h];
    __nv_bfloat16 hh, ll;
    split_bf16(xv * a + cx * (1.f - a), hh, ll);  kxh[idx] = hh; kxl[idx] = ll;
    split_bf16(xv * b + cx * (1.f - b), hh, ll);  vxh[idx] = hh; vxl[idx] = ll;
    split_bf16(xv * c + cx * (1.f - c), hh, ll);  rxh[idx] = hh; rxl[idx] = ll;
}

__global__ __launch_bounds__(256) void mix2_kernel(const float* __restrict__ x,
                                                   const float* __restrict__ tmk,
                                                   const float* __restrict__ tmr,
                                                   __nv_bfloat16* __restrict__ kxh, __nv_bfloat16* __restrict__ kxl,
                                                   __nv_bfloat16* __restrict__ rxh, __nv_bfloat16* __restrict__ rxl) {
    const int idx = blockIdx.x * 256 + threadIdx.x;
    const int h = idx & (H_DIM - 1);
    const float xv = x[idx];
    const float cx = (idx >= H_DIM) ? x[idx - H_DIM] : 0.f;
    const float a = tmk[h], c = tmr[h];
    __nv_bfloat16 hh, ll;
    split_bf16(xv * a + cx * (1.f - a), hh, ll);  kxh[idx] = hh; kxl[idx] = ll;
    split_bf16(xv * c + cx * (1.f - c), hh, ll);  rxh[idx] = hh; rxl[idx] = ll;
}

// ---------------- WKV serial scan with group-of-16 register prefetch ----------------
#define WKV_G 16
__global__ __launch_bounds__(256) void wkv_kernel(const float* __restrict__ k,
                                                  const float* __restrict__ v,
                                                  const float* __restrict__ r,
                                                  const float* __restrict__ time_first,
                                                  const float* __restrict__ time_decay,
                                                  __nv_bfloat16* __restrict__ outh,
                                                  __nv_bfloat16* __restrict__ outl) {
    const int h = blockIdx.x * 256 + threadIdx.x;
    const float u = time_first[h];
    const float w = -__expf(time_decay[h]);
    float aa = 0.f, bb = 0.f, pp = -CUDART_INF_F;

    float kb[WKV_G], vb[WKV_G], rb[WKV_G];
    for (int t0 = 0; t0 < T_SEQ; t0 += WKV_G) {
        const size_t base0 = (size_t)t0 * H_DIM + h;
#pragma unroll
        for (int j = 0; j < WKV_G; j++) {
            const size_t idx = base0 + (size_t)j * H_DIM;
            kb[j] = __ldg(&k[idx]);
            vb[j] = __ldg(&v[idx]);
            rb[j] = __ldg(&r[idx]);
        }
#pragma unroll
        for (int j = 0; j < WKV_G; j++) {
            const float kk = kb[j];
            const float vv = vb[j];
            const float ww = u + kk;
            const float p  = fmaxf(pp, ww);
            const float e1 = __expf(pp - p);
            const float e2 = __expf(ww - p);
            const float o  = rb[j] * __fdividef(e1 * aa + e2 * vv, e1 * bb + e2);
            __nv_bfloat16 hh, ll;
            split_bf16(o, hh, ll);
            const size_t idx = base0 + (size_t)j * H_DIM;
            outh[idx] = hh; outl[idx] = ll;
            const float ww2 = w + pp;
            const float p2  = fmaxf(ww2, kk);
            const float e1b = __expf(ww2 - p2);
            const float e2b = __expf(kk - p2);
            aa = e1b * aa + e2b * vv;
            bb = e1b * bb + e2b;
            pp = p2;
        }
    }
}

__global__ __launch_bounds__(256) void gate_add_kernel(float* __restrict__ out,
                                                       const float* __restrict__ rr,
                                                       const float* __restrict__ kv) {
    const int idx = blockIdx.x * 256 + threadIdx.x;
    out[idx] += rr[idx] * kv[idx];
}

// ---------------- launch ----------------
extern "C" void kernel_launch(void* const* d_in, const int* in_sizes, int n_in,
                              void* d_out, int out_size) {
    const float* hidden     = (const float*)d_in[0];
    const float* ln1_scale  = (const float*)d_in[1];
    const float* ln1_bias   = (const float*)d_in[2];
    const float* ln2_scale  = (const float*)d_in[3];
    const float* ln2_bias   = (const float*)d_in[4];
    const float* time_decay = (const float*)d_in[5];
    const float* time_first = (const float*)d_in[6];
    const float* tm_k       = (const float*)d_in[7];
    const float* tm_v       = (const float*)d_in[8];
    const float* tm_r       = (const float*)d_in[9];
    const float* Wk         = (const float*)d_in[10];
    const float* Wv         = (const float*)d_in[11];
    const float* Wr         = (const float*)d_in[12];
    const float* Wo         = (const float*)d_in[13];
    const float* ffn_tm_k   = (const float*)d_in[14];
    const float* ffn_tm_r   = (const float*)d_in[15];
    const float* Wk_ff      = (const float*)d_in[16];
    const float* Wv_ff      = (const float*)d_in[17];
    const float* Wr_ff      = (const float*)d_in[18];
    float* out = (float*)d_out;

    float *x, *k, *v, *r;
    __nv_bfloat16 *Ah, *Al, *Vh, *Vl, *Rh, *Rl, *Kh, *Kl, *Bh, *Bl;
    cudaGetSymbolAddress((void**)&x,  g_x);
    cudaGetSymbolAddress((void**)&k,  g_k);
    cudaGetSymbolAddress((void**)&v,  g_v);
    cudaGetSymbolAddress((void**)&r,  g_r);
    cudaGetSymbolAddress((void**)&Ah, g_Ah);
    cudaGetSymbolAddress((void**)&Al, g_Al);
    cudaGetSymbolAddress((void**)&Vh, g_Vh);
    cudaGetSymbolAddress((void**)&Vl, g_Vl);
    cudaGetSymbolAddress((void**)&Rh, g_Rh);
    cudaGetSymbolAddress((void**)&Rl, g_Rl);
    cudaGetSymbolAddress((void**)&Kh, g_Kh);
    cudaGetSymbolAddress((void**)&Kl, g_Kl);
    cudaGetSymbolAddress((void**)&Bh, g_Bh);
    cudaGetSymbolAddress((void**)&Bl, g_Bl);

    static const int SMEM_BYTES = 3 * STAGE_BYTES + 1024;   // 99328 -> 2 CTAs/SM
    cudaFuncSetAttribute(mma_gemm<0>, cudaFuncAttributeMaxDynamicSharedMemorySize, SMEM_BYTES);
    cudaFuncSetAttribute(mma_gemm<1>, cudaFuncAttributeMaxDynamicSharedMemorySize, SMEM_BYTES);
    cudaFuncSetAttribute(mma_gemm<3>, cudaFuncAttributeMaxDynamicSharedMemorySize, SMEM_BYTES);
    cudaFuncSetAttribute(mma_gemm<4>, cudaFuncAttributeMaxDynamicSharedMemorySize, SMEM_BYTES);

    const int ebH = (T_SEQ * H_DIM) / 256;
    const dim3 gHH(H_DIM / 128, T_SEQ / 128);   // (16, 32)
    const dim3 gHI(I_DIM / 128, T_SEQ / 128);   // (64, 32)
    const dim3 wtHH(H_DIM / 32, H_DIM / 32);
    const dim3 wtHI(I_DIM / 32, H_DIM / 32);
    const dim3 wtIH(H_DIM / 32, I_DIM / 32);

    // ---- time-mix ----
    ln_kernel<<<T_SEQ, 256>>>(hidden, ln1_scale, ln1_bias, x);
    mix3_kernel<<<ebH, 256>>>(x, tm_k, tm_v, tm_r, Ah, Al, Vh, Vl, Rh, Rl);

    convert_wt<<<wtHH, 256>>>(Wr, Bh, Bl, H_DIM, H_DIM);
    mma_gemm<1><<<gHH, 256, SMEM_BYTES>>>(Rh, Rl, Bh, Bl, r, nullptr, nullptr, nullptr, T_SEQ, H_DIM, H_DIM);

    convert_wt<<<wtHH, 256>>>(Wk, Bh, Bl, H_DIM, H_DIM);
    mma_gemm<0><<<gHH, 256, SMEM_BYTES>>>(Ah, Al, Bh, Bl, k, nullptr, nullptr, nullptr, T_SEQ, H_DIM, H_DIM);

    convert_wt<<<wtHH, 256>>>(Wv, Bh, Bl, H_DIM, H_DIM);
    mma_gemm<0><<<gHH, 256, SMEM_BYTES>>>(Vh, Vl, Bh, Bl, v, nullptr, nullptr, nullptr, T_SEQ, H_DIM, H_DIM);

    wkv_kernel<<<H_DIM / 256, 256>>>(k, v, r, time_first, time_decay, Ah, Al);  // r*wkv -> Ah/Al

    convert_wt<<<wtHH, 256>>>(Wo, Bh, Bl, H_DIM, H_DIM);
    mma_gemm<3><<<gHH, 256, SMEM_BYTES>>>(Ah, Al, Bh, Bl, out, hidden, nullptr, nullptr, T_SEQ, H_DIM, H_DIM);

    // ---- channel-mix ----
    ln_kernel<<<T_SEQ, 256>>>(out, ln2_scale, ln2_bias, x);
    mix2_kernel<<<ebH, 256>>>(x, ffn_tm_k, ffn_tm_r, Ah, Al, Rh, Rl);

    convert_wt<<<wtHH, 256>>>(Wr_ff, Bh, Bl, H_DIM, H_DIM);
    mma_gemm<1><<<gHH, 256, SMEM_BYTES>>>(Rh, Rl, Bh, Bl, r, nullptr, nullptr, nullptr, T_SEQ, H_DIM, H_DIM);

    convert_wt<<<wtHI, 256>>>(Wk_ff, Bh, Bl, H_DIM, I_DIM);
    mma_gemm<4><<<gHI, 256, SMEM_BYTES>>>(Ah, Al, Bh, Bl, nullptr, nullptr, Kh, Kl, T_SEQ, I_DIM, H_DIM);

    convert_wt<<<wtIH, 256>>>(Wv_ff, Bh, Bl, I_DIM, H_DIM);
    mma_gemm<0><<<gHH, 256, SMEM_BYTES>>>(Kh, Kl, Bh, Bl, v, nullptr, nullptr, nullptr, T_SEQ, H_DIM, I_DIM);

    gate_add_kernel<<<ebH, 256>>>(out, r, v);
}

// round 13
// speedup vs baseline: 1.2277x; 1.0740x over previous
#include <cuda_runtime.h>
#include <cuda_bf16.h>
#include <math_constants.h>
#include <cstdint>

#define T_SEQ 4096
#define H_DIM 2048
#define I_DIM 8192

// ---------------- scratch (device globals; no runtime allocation) ----------------
__device__ float g_x  [T_SEQ * H_DIM];       // LN output
__device__ float g_k  [T_SEQ * H_DIM];
__device__ float g_v  [T_SEQ * H_DIM];       // v, later kv
__device__ float g_r  [T_SEQ * H_DIM];       // sigmoid(r), later rr
// bf16 split activation buffers
__device__ __nv_bfloat16 g_Ah[(size_t)T_SEQ * H_DIM];  // kx / wkv / ffn-kx
__device__ __nv_bfloat16 g_Al[(size_t)T_SEQ * H_DIM];
__device__ __nv_bfloat16 g_Vh[(size_t)T_SEQ * H_DIM];  // vx
__device__ __nv_bfloat16 g_Vl[(size_t)T_SEQ * H_DIM];
__device__ __nv_bfloat16 g_Rh[(size_t)T_SEQ * H_DIM];  // rx / ffn-rx
__device__ __nv_bfloat16 g_Rl[(size_t)T_SEQ * H_DIM];
__device__ __nv_bfloat16 g_Kh[(size_t)T_SEQ * I_DIM];  // kk split (ffn inner)
__device__ __nv_bfloat16 g_Kl[(size_t)T_SEQ * I_DIM];
// weight split buffers (transposed, K-major)
__device__ __nv_bfloat16 g_Bh[(size_t)H_DIM * I_DIM];
__device__ __nv_bfloat16 g_Bl[(size_t)H_DIM * I_DIM];

// ---------------- helpers ----------------
__device__ __forceinline__ uint32_t smem_u32(const void* p) {
    uint32_t a;
    asm("{ .reg .u64 t; cvta.to.shared.u64 t, %1; cvt.u32.u64 %0, t; }" : "=r"(a) : "l"(p));
    return a;
}
#define SWZ128(o) ((o) ^ (((o) >> 3) & 0x70))

__device__ __forceinline__ void cp_async16(uint32_t dst, const void* src) {
    asm volatile("cp.async.cg.shared.global [%0], [%1], 16;" :: "r"(dst), "l"(src));
}
#define CP_COMMIT() asm volatile("cp.async.commit_group;" ::: "memory")

__device__ __forceinline__ void ldm_x4(uint32_t* r, uint32_t addr) {
    asm volatile("ldmatrix.sync.aligned.m8n8.x4.shared.b16 {%0,%1,%2,%3}, [%4];"
                 : "=r"(r[0]), "=r"(r[1]), "=r"(r[2]), "=r"(r[3]) : "r"(addr));
}
__device__ __forceinline__ void mma16816(float* c, const uint32_t* a, const uint32_t* b) {
    asm volatile(
        "mma.sync.aligned.m16n8k16.row.col.f32.bf16.bf16.f32 "
        "{%0,%1,%2,%3}, {%4,%5,%6,%7}, {%8,%9}, {%0,%1,%2,%3};"
        : "+f"(c[0]), "+f"(c[1]), "+f"(c[2]), "+f"(c[3])
        : "r"(a[0]), "r"(a[1]), "r"(a[2]), "r"(a[3]), "r"(b[0]), "r"(b[1]));
}
__device__ __forceinline__ void split_bf16(float v, __nv_bfloat16& h, __nv_bfloat16& l) {
    h = __float2bfloat16(v);
    l = __float2bfloat16(v - __bfloat162float(h));
}

// ---------------- mma.sync GEMM v3b: C[M,N] = A[M,K] @ B[N,K]^T  (3-term bf16 split) ---
// Same as v3 (BM=128/BN=128/BK=32, packed hi|lo rows, 3 stages, 3 passes/chunk) but with
// __launch_bounds__(256, 2): force regs<=128 so 2 CTAs/SM are restored (R12 hit 168 regs
// -> 1 CTA/SM -> unhidden barriers).
// EPI: 0=none 1=sigmoid 2=relu^2(fp32) 3=+=res 4=relu^2 -> bf16 hi/lo split
#define STAGE_BYTES 32768
template <int EPI>
__global__ __launch_bounds__(256, 2) void mma_gemm(const __nv_bfloat16* __restrict__ Ah,
                                                   const __nv_bfloat16* __restrict__ Al,
                                                   const __nv_bfloat16* __restrict__ Bh,
                                                   const __nv_bfloat16* __restrict__ Bl,
                                                   float* __restrict__ C,
                                                   const float* __restrict__ res,
                                                   __nv_bfloat16* __restrict__ Chi,
                                                   __nv_bfloat16* __restrict__ Clo,
                                                   int M, int N, int K) {
    extern __shared__ char dsm[];
    char* smem = (char*)(((uintptr_t)dsm + 1023u) & ~(uintptr_t)1023u);
    const uint32_t sbase = smem_u32(smem);

    const int tid = threadIdx.x;
    const int wid = tid >> 5, lane = tid & 31;
    const int warp_m = wid & 3;        // 4 warps along M (32 rows each)
    const int warp_n = wid >> 2;       // 2 warps along N (64 cols each)
    const int bm = blockIdx.y * 128, bn = blockIdx.x * 128;

    const int KC = K >> 5;             // 32-wide K chunks

    // ldmatrix per-lane coordinates
    const int a_row = (lane & 15);
    const int a_kb  = (lane >> 4) * 16;
    const int b_row = (lane & 7) + ((lane >> 4) << 3);
    const int b_kb  = ((lane >> 3) & 1) * 16;

    float acc[2][8][4];
#pragma unroll
    for (int i = 0; i < 2; i++)
#pragma unroll
        for (int j = 0; j < 8; j++)
#pragma unroll
            for (int q = 0; q < 4; q++) acc[i][j][q] = 0.f;

    // load chunk c (hi|lo packed rows for A and B) into stage p
    auto issue = [&](int c, int p) {
        const int k0 = c << 5;
        const uint32_t st = sbase + p * STAGE_BYTES;
#pragma unroll
        for (int j = 0; j < 4; j++) {
            const int i = tid + 256 * j;          // 0..1023
            const int row = i >> 3, seg = i & 7;  // 128 rows x 8 16B-segs
            const uint32_t off = SWZ128((uint32_t)(row * 128 + seg * 16));
            const int s4 = seg & 3;               // col segment within 32-col half
            const __nv_bfloat16* As = (seg < 4) ? Ah : Al;
            const __nv_bfloat16* Bs = (seg < 4) ? Bh : Bl;
            cp_async16(st + off,          As + (size_t)(bm + row) * K + k0 + s4 * 8);
            cp_async16(st + 16384 + off,  Bs + (size_t)(bn + row) * K + k0 + s4 * 8);
        }
        CP_COMMIT();
    };

    issue(0, 0);
    issue(1, 1);

    for (int c = 0; c < KC; c++) {
        if (c + 1 < KC) {
            asm volatile("cp.async.wait_group 1;" ::: "memory");
        } else {
            asm volatile("cp.async.wait_group 0;" ::: "memory");
        }
        __syncthreads();
        if (c + 2 < KC) issue(c + 2, (c + 2) % 3);

        const uint32_t st = sbase + (c % 3) * STAGE_BYTES;
        // 3 passes from the same stage: (Ah,Bh), (Al,Bh), (Ah,Bl)
#pragma unroll
        for (int pass = 0; pass < 3; pass++) {
            const uint32_t aofs = (pass == 1) ? 64u : 0u;   // lo half of A rows
            const uint32_t bofs = (pass == 2) ? 64u : 0u;   // lo half of B rows
#pragma unroll
            for (int ks = 0; ks < 2; ks++) {
                uint32_t afr[2][4];
#pragma unroll
                for (int mt = 0; mt < 2; mt++) {
                    const uint32_t off = (uint32_t)((warp_m * 32 + mt * 16 + a_row) * 128) + aofs + ks * 32 + a_kb;
                    ldm_x4(afr[mt], st + SWZ128(off));
                }
                uint32_t bfr[8][2];
#pragma unroll
                for (int np = 0; np < 4; np++) {
                    uint32_t r[4];
                    const uint32_t off = (uint32_t)((warp_n * 64 + np * 16 + b_row) * 128) + bofs + ks * 32 + b_kb;
                    ldm_x4(r, st + 16384u + SWZ128(off));
                    bfr[2 * np][0] = r[0];  bfr[2 * np][1] = r[1];
                    bfr[2 * np + 1][0] = r[2];  bfr[2 * np + 1][1] = r[3];
                }
#pragma unroll
                for (int mt = 0; mt < 2; mt++)
#pragma unroll
                    for (int nt = 0; nt < 8; nt++)
                        mma16816(acc[mt][nt], afr[mt], bfr[nt]);
            }
        }
        __syncthreads();
    }

    // ---- epilogue ----
    const int trow = lane >> 2;
    const int tcol = (lane & 3) * 2;
#pragma unroll
    for (int mt = 0; mt < 2; mt++) {
#pragma unroll
        for (int nt = 0; nt < 8; nt++) {
            const int row0 = bm + warp_m * 32 + mt * 16 + trow;
            const int col  = bn + warp_n * 64 + nt * 8 + tcol;
#pragma unroll
            for (int h = 0; h < 2; h++) {
                const int row = row0 + h * 8;
                float v0 = acc[mt][nt][2 * h + 0];
                float v1 = acc[mt][nt][2 * h + 1];
                const size_t base = (size_t)row * N + col;
                if (EPI == 1) {
                    v0 = 1.f / (1.f + __expf(-v0));
                    v1 = 1.f / (1.f + __expf(-v1));
                } else if (EPI == 2 || EPI == 4) {
                    v0 = fmaxf(v0, 0.f); v0 *= v0;
                    v1 = fmaxf(v1, 0.f); v1 *= v1;
                } else if (EPI == 3) {
                    const float2 rv = *reinterpret_cast<const float2*>(&res[base]);
                    v0 += rv.x; v1 += rv.y;
                }
                if (EPI == 4) {
                    __nv_bfloat16 h0, l0, h1, l1;
                    split_bf16(v0, h0, l0);
                    split_bf16(v1, h1, l1);
                    *reinterpret_cast<__nv_bfloat162*>(&Chi[base]) = __nv_bfloat162(h0, h1);
                    *reinterpret_cast<__nv_bfloat162*>(&Clo[base]) = __nv_bfloat162(l0, l1);
                } else {
                    *reinterpret_cast<float2*>(&C[base]) = make_float2(v0, v1);
                }
            }
        }
    }
}

// ---------------- weight transpose + split: W[K,N] fp32 -> [N,K] bf16 hi/lo ----------------
__global__ __launch_bounds__(256) void convert_wt(const float* __restrict__ W,
                                                  __nv_bfloat16* __restrict__ Th,
                                                  __nv_bfloat16* __restrict__ Tl,
                                                  int K, int N) {
    __shared__ float tile[32][33];
    const int tx = threadIdx.x & 31, ty = threadIdx.x >> 5;
    const int k0 = blockIdx.y * 32, n0 = blockIdx.x * 32;
#pragma unroll
    for (int j = 0; j < 4; j++)
        tile[ty + j * 8][tx] = W[(size_t)(k0 + ty + j * 8) * N + n0 + tx];
    __syncthreads();
#pragma unroll
    for (int j = 0; j < 4; j++) {
        const float v = tile[tx][ty + j * 8];
        __nv_bfloat16 h, l;
        split_bf16(v, h, l);
        const size_t o = (size_t)(n0 + ty + j * 8) * K + k0 + tx;
        Th[o] = h;
        Tl[o] = l;
    }
}

// ---------------- LayerNorm ----------------
__global__ __launch_bounds__(256) void ln_kernel(const float* __restrict__ in,
                                                 const float* __restrict__ sc,
                                                 const float* __restrict__ bi,
                                                 float* __restrict__ out) {
    __shared__ float red0[8], red1[8];
    const int t = blockIdx.x;
    const float* row = in + (size_t)t * H_DIM;
    float v[8];
    float s = 0.f, ss = 0.f;
#pragma unroll
    for (int i = 0; i < 8; i++) {
        v[i] = row[threadIdx.x + i * 256];
        s += v[i]; ss += v[i] * v[i];
    }
#pragma unroll
    for (int o = 16; o; o >>= 1) {
        s  += __shfl_xor_sync(0xffffffffu, s, o);
        ss += __shfl_xor_sync(0xffffffffu, ss, o);
    }
    const int w = threadIdx.x >> 5, l = threadIdx.x & 31;
    if (l == 0) { red0[w] = s; red1[w] = ss; }
    __syncthreads();
    if (threadIdx.x < 32) {
        s  = (l < 8) ? red0[l] : 0.f;
        ss = (l < 8) ? red1[l] : 0.f;
#pragma unroll
        for (int o = 4; o; o >>= 1) {
            s  += __shfl_xor_sync(0xffffffffu, s, o);
            ss += __shfl_xor_sync(0xffffffffu, ss, o);
        }
        if (l == 0) { red0[0] = s; red1[0] = ss; }
    }
    __syncthreads();
    const float mean = red0[0] * (1.f / H_DIM);
    const float var  = red1[0] * (1.f / H_DIM) - mean * mean;
    const float inv  = rsqrtf(var + 1e-5f);
    float* orow = out + (size_t)t * H_DIM;
#pragma unroll
    for (int i = 0; i < 8; i++) {
        const int h = threadIdx.x + i * 256;
        orow[h] = (v[i] - mean) * inv * sc[h] + bi[h];
    }
}

// ---------------- token-shift mixes, fused bf16 split output ----------------
__global__ __launch_bounds__(256) void mix3_kernel(const float* __restrict__ x,
                                                   const float* __restrict__ tmk,
                                                   const float* __restrict__ tmv,
                                                   const float* __restrict__ tmr,
                                                   __nv_bfloat16* __restrict__ kxh, __nv_bfloat16* __restrict__ kxl,
                                                   __nv_bfloat16* __restrict__ vxh, __nv_bfloat16* __restrict__ vxl,
                                                   __nv_bfloat16* __restrict__ rxh, __nv_bfloat16* __restrict__ rxl) {
    const int idx = blockIdx.x * 256 + threadIdx.x;
    const int h = idx & (H_DIM - 1);
    const float xv = x[idx];
    const float cx = (idx >= H_DIM) ? x[idx - H_DIM] : 0.f;
    const float a = tmk[h], b = tmv[h], c = tmr[h];
    __nv_bfloat16 hh, ll;
    split_bf16(xv * a + cx * (1.f - a), hh, ll);  kxh[idx] = hh; kxl[idx] = ll;
    split_bf16(xv * b + cx * (1.f - b), hh, ll);  vxh[idx] = hh; vxl[idx] = ll;
    split_bf16(xv * c + cx * (1.f - c), hh, ll);  rxh[idx] = hh; rxl[idx] = ll;
}

__global__ __launch_bounds__(256) void mix2_kernel(const float* __restrict__ x,
                                                   const float* __restrict__ tmk,
                                                   const float* __restrict__ tmr,
                                                   __nv_bfloat16* __restrict__ kxh, __nv_bfloat16* __restrict__ kxl,
                                                   __nv_bfloat16* __restrict__ rxh, __nv_bfloat16* __restrict__ rxl) {
    const int idx = blockIdx.x * 256 + threadIdx.x;
    const int h = idx & (H_DIM - 1);
    const float xv = x[idx];
    const float cx = (idx >= H_DIM) ? x[idx - H_DIM] : 0.f;
    const float a = tmk[h], c = tmr[h];
    __nv_bfloat16 hh, ll;
    split_bf16(xv * a + cx * (1.f - a), hh, ll);  kxh[idx] = hh; kxl[idx] = ll;
    split_bf16(xv * c + cx * (1.f - c), hh, ll);  rxh[idx] = hh; rxl[idx] = ll;
}

// ---------------- WKV serial scan with group-of-16 register prefetch ----------------
#define WKV_G 16
__global__ __launch_bounds__(256) void wkv_kernel(const float* __restrict__ k,
                                                  const float* __restrict__ v,
                                                  const float* __restrict__ r,
                                                  const float* __restrict__ time_first,
                                                  const float* __restrict__ time_decay,
                                                  __nv_bfloat16* __restrict__ outh,
                                                  __nv_bfloat16* __restrict__ outl) {
    const int h = blockIdx.x * 256 + threadIdx.x;
    const float u = time_first[h];
    const float w = -__expf(time_decay[h]);
    float aa = 0.f, bb = 0.f, pp = -CUDART_INF_F;

    float kb[WKV_G], vb[WKV_G], rb[WKV_G];
    for (int t0 = 0; t0 < T_SEQ; t0 += WKV_G) {
        const size_t base0 = (size_t)t0 * H_DIM + h;
#pragma unroll
        for (int j = 0; j < WKV_G; j++) {
            const size_t idx = base0 + (size_t)j * H_DIM;
            kb[j] = __ldg(&k[idx]);
            vb[j] = __ldg(&v[idx]);
            rb[j] = __ldg(&r[idx]);
        }
#pragma unroll
        for (int j = 0; j < WKV_G; j++) {
            const float kk = kb[j];
            const float vv = vb[j];
            const float ww = u + kk;
            const float p  = fmaxf(pp, ww);
            const float e1 = __expf(pp - p);
            const float e2 = __expf(ww - p);
            const float o  = rb[j] * __fdividef(e1 * aa + e2 * vv, e1 * bb + e2);
            __nv_bfloat16 hh, ll;
            split_bf16(o, hh, ll);
            const size_t idx = base0 + (size_t)j * H_DIM;
            outh[idx] = hh; outl[idx] = ll;
            const float ww2 = w + pp;
            const float p2  = fmaxf(ww2, kk);
            const float e1b = __expf(ww2 - p2);
            const float e2b = __expf(kk - p2);
            aa = e1b * aa + e2b * vv;
            bb = e1b * bb + e2b;
            pp = p2;
        }
    }
}

__global__ __launch_bounds__(256) void gate_add_kernel(float* __restrict__ out,
                                                       const float* __restrict__ rr,
                                                       const float* __restrict__ kv) {
    const int idx = blockIdx.x * 256 + threadIdx.x;
    out[idx] += rr[idx] * kv[idx];
}

// ---------------- launch ----------------
extern "C" void kernel_launch(void* const* d_in, const int* in_sizes, int n_in,
                              void* d_out, int out_size) {
    const float* hidden     = (const float*)d_in[0];
    const float* ln1_scale  = (const float*)d_in[1];
    const float* ln1_bias   = (const float*)d_in[2];
    const float* ln2_scale  = (const float*)d_in[3];
    const float* ln2_bias   = (const float*)d_in[4];
    const float* time_decay = (const float*)d_in[5];
    const float* time_first = (const float*)d_in[6];
    const float* tm_k       = (const float*)d_in[7];
    const float* tm_v       = (const float*)d_in[8];
    const float* tm_r       = (const float*)d_in[9];
    const float* Wk         = (const float*)d_in[10];
    const float* Wv         = (const float*)d_in[11];
    const float* Wr         = (const float*)d_in[12];
    const float* Wo         = (const float*)d_in[13];
    const float* ffn_tm_k   = (const float*)d_in[14];
    const float* ffn_tm_r   = (const float*)d_in[15];
    const float* Wk_ff      = (const float*)d_in[16];
    const float* Wv_ff      = (const float*)d_in[17];
    const float* Wr_ff      = (const float*)d_in[18];
    float* out = (float*)d_out;

    float *x, *k, *v, *r;
    __nv_bfloat16 *Ah, *Al, *Vh, *Vl, *Rh, *Rl, *Kh, *Kl, *Bh, *Bl;
    cudaGetSymbolAddress((void**)&x,  g_x);
    cudaGetSymbolAddress((void**)&k,  g_k);
    cudaGetSymbolAddress((void**)&v,  g_v);
    cudaGetSymbolAddress((void**)&r,  g_r);
    cudaGetSymbolAddress((void**)&Ah, g_Ah);
    cudaGetSymbolAddress((void**)&Al, g_Al);
    cudaGetSymbolAddress((void**)&Vh, g_Vh);
    cudaGetSymbolAddress((void**)&Vl, g_Vl);
    cudaGetSymbolAddress((void**)&Rh, g_Rh);
    cudaGetSymbolAddress((void**)&Rl, g_Rl);
    cudaGetSymbolAddress((void**)&Kh, g_Kh);
    cudaGetSymbolAddress((void**)&Kl, g_Kl);
    cudaGetSymbolAddress((void**)&Bh, g_Bh);
    cudaGetSymbolAddress((void**)&Bl, g_Bl);

    static const int SMEM_BYTES = 3 * STAGE_BYTES + 1024;   // 99328 -> 2 CTAs/SM
    cudaFuncSetAttribute(mma_gemm<0>, cudaFuncAttributeMaxDynamicSharedMemorySize, SMEM_BYTES);
    cudaFuncSetAttribute(mma_gemm<1>, cudaFuncAttributeMaxDynamicSharedMemorySize, SMEM_BYTES);
    cudaFuncSetAttribute(mma_gemm<3>, cudaFuncAttributeMaxDynamicSharedMemorySize, SMEM_BYTES);
    cudaFuncSetAttribute(mma_gemm<4>, cudaFuncAttributeMaxDynamicSharedMemorySize, SMEM_BYTES);

    const int ebH = (T_SEQ * H_DIM) / 256;
    const dim3 gHH(H_DIM / 128, T_SEQ / 128);   // (16, 32)
    const dim3 gHI(I_DIM / 128, T_SEQ / 128);   // (64, 32)
    const dim3 wtHH(H_DIM / 32, H_DIM / 32);
    const dim3 wtHI(I_DIM / 32, H_DIM / 32);
    const dim3 wtIH(H_DIM / 32, I_DIM / 32);

    // ---- time-mix ----
    ln_kernel<<<T_SEQ, 256>>>(hidden, ln1_scale, ln1_bias, x);
    mix3_kernel<<<ebH, 256>>>(x, tm_k, tm_v, tm_r, Ah, Al, Vh, Vl, Rh, Rl);

    convert_wt<<<wtHH, 256>>>(Wr, Bh, Bl, H_DIM, H_DIM);
    mma_gemm<1><<<gHH, 256, SMEM_BYTES>>>(Rh, Rl, Bh, Bl, r, nullptr, nullptr, nullptr, T_SEQ, H_DIM, H_DIM);

    convert_wt<<<wtHH, 256>>>(Wk, Bh, Bl, H_DIM, H_DIM);
    mma_gemm<0><<<gHH, 256, SMEM_BYTES>>>(Ah, Al, Bh, Bl, k, nullptr, nullptr, nullptr, T_SEQ, H_DIM, H_DIM);

    convert_wt<<<wtHH, 256>>>(Wv, Bh, Bl, H_DIM, H_DIM);
    mma_gemm<0><<<gHH, 256, SMEM_BYTES>>>(Vh, Vl, Bh, Bl, v, nullptr, nullptr, nullptr, T_SEQ, H_DIM, H_DIM);

    wkv_kernel<<<H_DIM / 256, 256>>>(k, v, r, time_first, time_decay, Ah, Al);  // r*wkv -> Ah/Al

    convert_wt<<<wtHH, 256>>>(Wo, Bh, Bl, H_DIM, H_DIM);
    mma_gemm<3><<<gHH, 256, SMEM_BYTES>>>(Ah, Al, Bh, Bl, out, hidden, nullptr, nullptr, T_SEQ, H_DIM, H_DIM);

    // ---- channel-mix ----
    ln_kernel<<<T_SEQ, 256>>>(out, ln2_scale, ln2_bias, x);
    mix2_kernel<<<ebH, 256>>>(x, ffn_tm_k, ffn_tm_r, Ah, Al, Rh, Rl);

    convert_wt<<<wtHH, 256>>>(Wr_ff, Bh, Bl, H_DIM, H_DIM);
    mma_gemm<1><<<gHH, 256, SMEM_BYTES>>>(Rh, Rl, Bh, Bl, r, nullptr, nullptr, nullptr, T_SEQ, H_DIM, H_DIM);

    convert_wt<<<wtHI, 256>>>(Wk_ff, Bh, Bl, H_DIM, I_DIM);
    mma_gemm<4><<<gHI, 256, SMEM_BYTES>>>(Ah, Al, Bh, Bl, nullptr, nullptr, Kh, Kl, T_SEQ, I_DIM, H_DIM);

    convert_wt<<<wtIH, 256>>>(Wv_ff, Bh, Bl, I_DIM, H_DIM);
    mma_gemm<0><<<gHH, 256, SMEM_BYTES>>>(Kh, Kl, Bh, Bl, v, nullptr, nullptr, nullptr, T_SEQ, H_DIM, I_DIM);

    gate_add_kernel<<<ebH, 256>>>(out, r, v);
}

// round 14
// speedup vs baseline: 1.2866x; 1.0480x over previous
#include <cuda_runtime.h>
#include <cuda_bf16.h>
#include <math_constants.h>
#include <cstdint>

#define T_SEQ 4096
#define H_DIM 2048
#define I_DIM 8192

// ---------------- scratch (device globals; no runtime allocation) ----------------
__device__ float g_x  [T_SEQ * H_DIM];       // LN output
__device__ float g_k  [T_SEQ * H_DIM];
__device__ float g_v  [T_SEQ * H_DIM];       // v, later kv
__device__ float g_r  [T_SEQ * H_DIM];       // sigmoid(r), later rr
// bf16 split activation buffers
__device__ __nv_bfloat16 g_Ah[(size_t)T_SEQ * H_DIM];  // kx / wkv / ffn-kx
__device__ __nv_bfloat16 g_Al[(size_t)T_SEQ * H_DIM];
__device__ __nv_bfloat16 g_Vh[(size_t)T_SEQ * H_DIM];  // vx
__device__ __nv_bfloat16 g_Vl[(size_t)T_SEQ * H_DIM];
__device__ __nv_bfloat16 g_Rh[(size_t)T_SEQ * H_DIM];  // rx / ffn-rx
__device__ __nv_bfloat16 g_Rl[(size_t)T_SEQ * H_DIM];
__device__ __nv_bfloat16 g_Kh[(size_t)T_SEQ * I_DIM];  // kk split (ffn inner)
__device__ __nv_bfloat16 g_Kl[(size_t)T_SEQ * I_DIM];
// per-weight split buffers (transposed, K-major) — converts run on a side stream
__device__ __nv_bfloat16 g_Wr_h [(size_t)H_DIM * H_DIM];
__device__ __nv_bfloat16 g_Wr_l [(size_t)H_DIM * H_DIM];
__device__ __nv_bfloat16 g_Wk_h [(size_t)H_DIM * H_DIM];
__device__ __nv_bfloat16 g_Wk_l [(size_t)H_DIM * H_DIM];
__device__ __nv_bfloat16 g_Wv_h [(size_t)H_DIM * H_DIM];
__device__ __nv_bfloat16 g_Wv_l [(size_t)H_DIM * H_DIM];
__device__ __nv_bfloat16 g_Wo_h [(size_t)H_DIM * H_DIM];
__device__ __nv_bfloat16 g_Wo_l [(size_t)H_DIM * H_DIM];
__device__ __nv_bfloat16 g_Wrf_h[(size_t)H_DIM * H_DIM];
__device__ __nv_bfloat16 g_Wrf_l[(size_t)H_DIM * H_DIM];
__device__ __nv_bfloat16 g_Wkf_h[(size_t)H_DIM * I_DIM];
__device__ __nv_bfloat16 g_Wkf_l[(size_t)H_DIM * I_DIM];
__device__ __nv_bfloat16 g_Wvf_h[(size_t)H_DIM * I_DIM];
__device__ __nv_bfloat16 g_Wvf_l[(size_t)H_DIM * I_DIM];

// ---------------- helpers ----------------
__device__ __forceinline__ uint32_t smem_u32(const void* p) {
    uint32_t a;
    asm("{ .reg .u64 t; cvta.to.shared.u64 t, %1; cvt.u32.u64 %0, t; }" : "=r"(a) : "l"(p));
    return a;
}
#define SWZ128(o) ((o) ^ (((o) >> 3) & 0x70))

__device__ __forceinline__ void cp_async16(uint32_t dst, const void* src) {
    asm volatile("cp.async.cg.shared.global [%0], [%1], 16;" :: "r"(dst), "l"(src));
}
#define CP_COMMIT() asm volatile("cp.async.commit_group;" ::: "memory")

__device__ __forceinline__ void ldm_x4(uint32_t* r, uint32_t addr) {
    asm volatile("ldmatrix.sync.aligned.m8n8.x4.shared.b16 {%0,%1,%2,%3}, [%4];"
                 : "=r"(r[0]), "=r"(r[1]), "=r"(r[2]), "=r"(r[3]) : "r"(addr));
}
__device__ __forceinline__ void mma16816(float* c, const uint32_t* a, const uint32_t* b) {
    asm volatile(
        "mma.sync.aligned.m16n8k16.row.col.f32.bf16.bf16.f32 "
        "{%0,%1,%2,%3}, {%4,%5,%6,%7}, {%8,%9}, {%0,%1,%2,%3};"
        : "+f"(c[0]), "+f"(c[1]), "+f"(c[2]), "+f"(c[3])
        : "r"(a[0]), "r"(a[1]), "r"(a[2]), "r"(a[3]), "r"(b[0]), "r"(b[1]));
}
__device__ __forceinline__ void split_bf16(float v, __nv_bfloat16& h, __nv_bfloat16& l) {
    h = __float2bfloat16(v);
    l = __float2bfloat16(v - __bfloat162float(h));
}

// ---------------- mma.sync GEMM v3b (unchanged from R13) ----------------
// BM=128/BN=128/BK=32, packed hi|lo rows, 3 stages, 3 passes/chunk, launch_bounds(256,2).
// EPI: 0=none 1=sigmoid 2=relu^2(fp32) 3=+=res 4=relu^2 -> bf16 hi/lo split
#define STAGE_BYTES 32768
template <int EPI>
__global__ __launch_bounds__(256, 2) void mma_gemm(const __nv_bfloat16* __restrict__ Ah,
                                                   const __nv_bfloat16* __restrict__ Al,
                                                   const __nv_bfloat16* __restrict__ Bh,
                                                   const __nv_bfloat16* __restrict__ Bl,
                                                   float* __restrict__ C,
                                                   const float* __restrict__ res,
                                                   __nv_bfloat16* __restrict__ Chi,
                                                   __nv_bfloat16* __restrict__ Clo,
                                                   int M, int N, int K) {
    extern __shared__ char dsm[];
    char* smem = (char*)(((uintptr_t)dsm + 1023u) & ~(uintptr_t)1023u);
    const uint32_t sbase = smem_u32(smem);

    const int tid = threadIdx.x;
    const int wid = tid >> 5, lane = tid & 31;
    const int warp_m = wid & 3;
    const int warp_n = wid >> 2;
    const int bm = blockIdx.y * 128, bn = blockIdx.x * 128;

    const int KC = K >> 5;

    const int a_row = (lane & 15);
    const int a_kb  = (lane >> 4) * 16;
    const int b_row = (lane & 7) + ((lane >> 4) << 3);
    const int b_kb  = ((lane >> 3) & 1) * 16;

    float acc[2][8][4];
#pragma unroll
    for (int i = 0; i < 2; i++)
#pragma unroll
        for (int j = 0; j < 8; j++)
#pragma unroll
            for (int q = 0; q < 4; q++) acc[i][j][q] = 0.f;

    auto issue = [&](int c, int p) {
        const int k0 = c << 5;
        const uint32_t st = sbase + p * STAGE_BYTES;
#pragma unroll
        for (int j = 0; j < 4; j++) {
            const int i = tid + 256 * j;
            const int row = i >> 3, seg = i & 7;
            const uint32_t off = SWZ128((uint32_t)(row * 128 + seg * 16));
            const int s4 = seg & 3;
            const __nv_bfloat16* As = (seg < 4) ? Ah : Al;
            const __nv_bfloat16* Bs = (seg < 4) ? Bh : Bl;
            cp_async16(st + off,          As + (size_t)(bm + row) * K + k0 + s4 * 8);
            cp_async16(st + 16384 + off,  Bs + (size_t)(bn + row) * K + k0 + s4 * 8);
        }
        CP_COMMIT();
    };

    issue(0, 0);
    issue(1, 1);

    for (int c = 0; c < KC; c++) {
        if (c + 1 < KC) {
            asm volatile("cp.async.wait_group 1;" ::: "memory");
        } else {
            asm volatile("cp.async.wait_group 0;" ::: "memory");
        }
        __syncthreads();
        if (c + 2 < KC) issue(c + 2, (c + 2) % 3);

        const uint32_t st = sbase + (c % 3) * STAGE_BYTES;
#pragma unroll
        for (int pass = 0; pass < 3; pass++) {
            const uint32_t aofs = (pass == 1) ? 64u : 0u;
            const uint32_t bofs = (pass == 2) ? 64u : 0u;
#pragma unroll
            for (int ks = 0; ks < 2; ks++) {
                uint32_t afr[2][4];
#pragma unroll
                for (int mt = 0; mt < 2; mt++) {
                    const uint32_t off = (uint32_t)((warp_m * 32 + mt * 16 + a_row) * 128) + aofs + ks * 32 + a_kb;
                    ldm_x4(afr[mt], st + SWZ128(off));
                }
                uint32_t bfr[8][2];
#pragma unroll
                for (int np = 0; np < 4; np++) {
                    uint32_t r[4];
                    const uint32_t off = (uint32_t)((warp_n * 64 + np * 16 + b_row) * 128) + bofs + ks * 32 + b_kb;
                    ldm_x4(r, st + 16384u + SWZ128(off));
                    bfr[2 * np][0] = r[0];  bfr[2 * np][1] = r[1];
                    bfr[2 * np + 1][0] = r[2];  bfr[2 * np + 1][1] = r[3];
                }
#pragma unroll
                for (int mt = 0; mt < 2; mt++)
#pragma unroll
                    for (int nt = 0; nt < 8; nt++)
                        mma16816(acc[mt][nt], afr[mt], bfr[nt]);
            }
        }
        __syncthreads();
    }

    const int trow = lane >> 2;
    const int tcol = (lane & 3) * 2;
#pragma unroll
    for (int mt = 0; mt < 2; mt++) {
#pragma unroll
        for (int nt = 0; nt < 8; nt++) {
            const int row0 = bm + warp_m * 32 + mt * 16 + trow;
            const int col  = bn + warp_n * 64 + nt * 8 + tcol;
#pragma unroll
            for (int h = 0; h < 2; h++) {
                const int row = row0 + h * 8;
                float v0 = acc[mt][nt][2 * h + 0];
                float v1 = acc[mt][nt][2 * h + 1];
                const size_t base = (size_t)row * N + col;
                if (EPI == 1) {
                    v0 = 1.f / (1.f + __expf(-v0));
                    v1 = 1.f / (1.f + __expf(-v1));
                } else if (EPI == 2 || EPI == 4) {
                    v0 = fmaxf(v0, 0.f); v0 *= v0;
                    v1 = fmaxf(v1, 0.f); v1 *= v1;
                } else if (EPI == 3) {
                    const float2 rv = *reinterpret_cast<const float2*>(&res[base]);
                    v0 += rv.x; v1 += rv.y;
                }
                if (EPI == 4) {
                    __nv_bfloat16 h0, l0, h1, l1;
                    split_bf16(v0, h0, l0);
                    split_bf16(v1, h1, l1);
                    *reinterpret_cast<__nv_bfloat162*>(&Chi[base]) = __nv_bfloat162(h0, h1);
                    *reinterpret_cast<__nv_bfloat162*>(&Clo[base]) = __nv_bfloat162(l0, l1);
                } else {
                    *reinterpret_cast<float2*>(&C[base]) = make_float2(v0, v1);
                }
            }
        }
    }
}

// ---------------- weight transpose + split: W[K,N] fp32 -> [N,K] bf16 hi/lo ----------------
__global__ __launch_bounds__(256) void convert_wt(const float* __restrict__ W,
                                                  __nv_bfloat16* __restrict__ Th,
                                                  __nv_bfloat16* __restrict__ Tl,
                                                  int K, int N) {
    __shared__ float tile[32][33];
    const int tx = threadIdx.x & 31, ty = threadIdx.x >> 5;
    const int k0 = blockIdx.y * 32, n0 = blockIdx.x * 32;
#pragma unroll
    for (int j = 0; j < 4; j++)
        tile[ty + j * 8][tx] = W[(size_t)(k0 + ty + j * 8) * N + n0 + tx];
    __syncthreads();
#pragma unroll
    for (int j = 0; j < 4; j++) {
        const float v = tile[tx][ty + j * 8];
        __nv_bfloat16 h, l;
        split_bf16(v, h, l);
        const size_t o = (size_t)(n0 + ty + j * 8) * K + k0 + tx;
        Th[o] = h;
        Tl[o] = l;
    }
}

// ---------------- LayerNorm ----------------
__global__ __launch_bounds__(256) void ln_kernel(const float* __restrict__ in,
                                                 const float* __restrict__ sc,
                                                 const float* __restrict__ bi,
                                                 float* __restrict__ out) {
    __shared__ float red0[8], red1[8];
    const int t = blockIdx.x;
    const float* row = in + (size_t)t * H_DIM;
    float v[8];
    float s = 0.f, ss = 0.f;
#pragma unroll
    for (int i = 0; i < 8; i++) {
        v[i] = row[threadIdx.x + i * 256];
        s += v[i]; ss += v[i] * v[i];
    }
#pragma unroll
    for (int o = 16; o; o >>= 1) {
        s  += __shfl_xor_sync(0xffffffffu, s, o);
        ss += __shfl_xor_sync(0xffffffffu, ss, o);
    }
    const int w = threadIdx.x >> 5, l = threadIdx.x & 31;
    if (l == 0) { red0[w] = s; red1[w] = ss; }
    __syncthreads();
    if (threadIdx.x < 32) {
        s  = (l < 8) ? red0[l] : 0.f;
        ss = (l < 8) ? red1[l] : 0.f;
#pragma unroll
        for (int o = 4; o; o >>= 1) {
            s  += __shfl_xor_sync(0xffffffffu, s, o);
            ss += __shfl_xor_sync(0xffffffffu, ss, o);
        }
        if (l == 0) { red0[0] = s; red1[0] = ss; }
    }
    __syncthreads();
    const float mean = red0[0] * (1.f / H_DIM);
    const float var  = red1[0] * (1.f / H_DIM) - mean * mean;
    const float inv  = rsqrtf(var + 1e-5f);
    float* orow = out + (size_t)t * H_DIM;
#pragma unroll
    for (int i = 0; i < 8; i++) {
        const int h = threadIdx.x + i * 256;
        orow[h] = (v[i] - mean) * inv * sc[h] + bi[h];
    }
}

// ---------------- token-shift mixes, fused bf16 split output ----------------
__global__ __launch_bounds__(256) void mix3_kernel(const float* __restrict__ x,
                                                   const float* __restrict__ tmk,
                                                   const float* __restrict__ tmv,
                                                   const float* __restrict__ tmr,
                                                   __nv_bfloat16* __restrict__ kxh, __nv_bfloat16* __restrict__ kxl,
                                                   __nv_bfloat16* __restrict__ vxh, __nv_bfloat16* __restrict__ vxl,
                                                   __nv_bfloat16* __restrict__ rxh, __nv_bfloat16* __restrict__ rxl) {
    const int idx = blockIdx.x * 256 + threadIdx.x;
    const int h = idx & (H_DIM - 1);
    const float xv = x[idx];
    const float cx = (idx >= H_DIM) ? x[idx - H_DIM] : 0.f;
    const float a = tmk[h], b = tmv[h], c = tmr[h];
    __nv_bfloat16 hh, ll;
    split_bf16(xv * a + cx * (1.f - a), hh, ll);  kxh[idx] = hh; kxl[idx] = ll;
    split_bf16(xv * b + cx * (1.f - b), hh, ll);  vxh[idx] = hh; vxl[idx] = ll;
    split_bf16(xv * c + cx * (1.f - c), hh, ll);  rxh[idx] = hh; rxl[idx] = ll;
}

__global__ __launch_bounds__(256) void mix2_kernel(const float* __restrict__ x,
                                                   const float* __restrict__ tmk,
                                                   const float* __restrict__ tmr,
                                                   __nv_bfloat16* __restrict__ kxh, __nv_bfloat16* __restrict__ kxl,
                                                   __nv_bfloat16* __restrict__ rxh, __nv_bfloat16* __restrict__ rxl) {
    const int idx = blockIdx.x * 256 + threadIdx.x;
    const int h = idx & (H_DIM - 1);
    const float xv = x[idx];
    const float cx = (idx >= H_DIM) ? x[idx - H_DIM] : 0.f;
    const float a = tmk[h], c = tmr[h];
    __nv_bfloat16 hh, ll;
    split_bf16(xv * a + cx * (1.f - a), hh, ll);  kxh[idx] = hh; kxl[idx] = ll;
    split_bf16(xv * c + cx * (1.f - c), hh, ll);  rxh[idx] = hh; rxl[idx] = ll;
}

// ---------------- WKV serial scan with group-of-16 register prefetch ----------------
#define WKV_G 16
__global__ __launch_bounds__(256) void wkv_kernel(const float* __restrict__ k,
                                                  const float* __restrict__ v,
                                                  const float* __restrict__ r,
                                                  const float* __restrict__ time_first,
                                                  const float* __restrict__ time_decay,
                                                  __nv_bfloat16* __restrict__ outh,
                                                  __nv_bfloat16* __restrict__ outl) {
    const int h = blockIdx.x * 256 + threadIdx.x;
    const float u = time_first[h];
    const float w = -__expf(time_decay[h]);
    float aa = 0.f, bb = 0.f, pp = -CUDART_INF_F;

    float kb[WKV_G], vb[WKV_G], rb[WKV_G];
    for (int t0 = 0; t0 < T_SEQ; t0 += WKV_G) {
        const size_t base0 = (size_t)t0 * H_DIM + h;
#pragma unroll
        for (int j = 0; j < WKV_G; j++) {
            const size_t idx = base0 + (size_t)j * H_DIM;
            kb[j] = __ldg(&k[idx]);
            vb[j] = __ldg(&v[idx]);
            rb[j] = __ldg(&r[idx]);
        }
#pragma unroll
        for (int j = 0; j < WKV_G; j++) {
            const float kk = kb[j];
            const float vv = vb[j];
            const float ww = u + kk;
            const float p  = fmaxf(pp, ww);
            const float e1 = __expf(pp - p);
            const float e2 = __expf(ww - p);
            const float o  = rb[j] * __fdividef(e1 * aa + e2 * vv, e1 * bb + e2);
            __nv_bfloat16 hh, ll;
            split_bf16(o, hh, ll);
            const size_t idx = base0 + (size_t)j * H_DIM;
            outh[idx] = hh; outl[idx] = ll;
            const float ww2 = w + pp;
            const float p2  = fmaxf(ww2, kk);
            const float e1b = __expf(ww2 - p2);
            const float e2b = __expf(kk - p2);
            aa = e1b * aa + e2b * vv;
            bb = e1b * bb + e2b;
            pp = p2;
        }
    }
}

__global__ __launch_bounds__(256) void gate_add_kernel(float* __restrict__ out,
                                                       const float* __restrict__ rr,
                                                       const float* __restrict__ kv) {
    const int idx = blockIdx.x * 256 + threadIdx.x;
    out[idx] += rr[idx] * kv[idx];
}

// ---------------- launch ----------------
extern "C" void kernel_launch(void* const* d_in, const int* in_sizes, int n_in,
                              void* d_out, int out_size) {
    const float* hidden     = (const float*)d_in[0];
    const float* ln1_scale  = (const float*)d_in[1];
    const float* ln1_bias   = (const float*)d_in[2];
    const float* ln2_scale  = (const float*)d_in[3];
    const float* ln2_bias   = (const float*)d_in[4];
    const float* time_decay = (const float*)d_in[5];
    const float* time_first = (const float*)d_in[6];
    const float* tm_k       = (const float*)d_in[7];
    const float* tm_v       = (const float*)d_in[8];
    const float* tm_r       = (const float*)d_in[9];
    const float* Wk         = (const float*)d_in[10];
    const float* Wv         = (const float*)d_in[11];
    const float* Wr         = (const float*)d_in[12];
    const float* Wo         = (const float*)d_in[13];
    const float* ffn_tm_k   = (const float*)d_in[14];
    const float* ffn_tm_r   = (const float*)d_in[15];
    const float* Wk_ff      = (const float*)d_in[16];
    const float* Wv_ff      = (const float*)d_in[17];
    const float* Wr_ff      = (const float*)d_in[18];
    float* out = (float*)d_out;

    float *x, *k, *v, *r;
    __nv_bfloat16 *Ah, *Al, *Vh, *Vl, *Rh, *Rl, *Kh, *Kl;
    __nv_bfloat16 *Wrh, *Wrl, *Wkh, *Wkl, *Wvh, *Wvl, *Woh, *Wol, *Wrfh, *Wrfl, *Wkfh, *Wkfl, *Wvfh, *Wvfl;
    cudaGetSymbolAddress((void**)&x,  g_x);
    cudaGetSymbolAddress((void**)&k,  g_k);
    cudaGetSymbolAddress((void**)&v,  g_v);
    cudaGetSymbolAddress((void**)&r,  g_r);
    cudaGetSymbolAddress((void**)&Ah, g_Ah);
    cudaGetSymbolAddress((void**)&Al, g_Al);
    cudaGetSymbolAddress((void**)&Vh, g_Vh);
    cudaGetSymbolAddress((void**)&Vl, g_Vl);
    cudaGetSymbolAddress((void**)&Rh, g_Rh);
    cudaGetSymbolAddress((void**)&Rl, g_Rl);
    cudaGetSymbolAddress((void**)&Kh, g_Kh);
    cudaGetSymbolAddress((void**)&Kl, g_Kl);
    cudaGetSymbolAddress((void**)&Wrh,  g_Wr_h);   cudaGetSymbolAddress((void**)&Wrl,  g_Wr_l);
    cudaGetSymbolAddress((void**)&Wkh,  g_Wk_h);   cudaGetSymbolAddress((void**)&Wkl,  g_Wk_l);
    cudaGetSymbolAddress((void**)&Wvh,  g_Wv_h);   cudaGetSymbolAddress((void**)&Wvl,  g_Wv_l);
    cudaGetSymbolAddress((void**)&Woh,  g_Wo_h);   cudaGetSymbolAddress((void**)&Wol,  g_Wo_l);
    cudaGetSymbolAddress((void**)&Wrfh, g_Wrf_h);  cudaGetSymbolAddress((void**)&Wrfl, g_Wrf_l);
    cudaGetSymbolAddress((void**)&Wkfh, g_Wkf_h);  cudaGetSymbolAddress((void**)&Wkfl, g_Wkf_l);
    cudaGetSymbolAddress((void**)&Wvfh, g_Wvf_h);  cudaGetSymbolAddress((void**)&Wvfl, g_Wvf_l);

    static const int SMEM_BYTES = 3 * STAGE_BYTES + 1024;   // 99328 -> 2 CTAs/SM
    static bool s_init = false;
    static cudaStream_t sW, s3, s4;
    static cudaEvent_t eFork, eMix, eWr, eWk, eWv, eWo, eWrf, eWkf, eWvf, eGk, eGv, eGrr, eMix2;
    if (!s_init) {
        cudaFuncSetAttribute(mma_gemm<0>, cudaFuncAttributeMaxDynamicSharedMemorySize, SMEM_BYTES);
        cudaFuncSetAttribute(mma_gemm<1>, cudaFuncAttributeMaxDynamicSharedMemorySize, SMEM_BYTES);
        cudaFuncSetAttribute(mma_gemm<3>, cudaFuncAttributeMaxDynamicSharedMemorySize, SMEM_BYTES);
        cudaFuncSetAttribute(mma_gemm<4>, cudaFuncAttributeMaxDynamicSharedMemorySize, SMEM_BYTES);
        cudaStreamCreateWithFlags(&sW, cudaStreamNonBlocking);
        cudaStreamCreateWithFlags(&s3, cudaStreamNonBlocking);
        cudaStreamCreateWithFlags(&s4, cudaStreamNonBlocking);
        cudaEventCreateWithFlags(&eFork, cudaEventDisableTiming);
        cudaEventCreateWithFlags(&eMix,  cudaEventDisableTiming);
        cudaEventCreateWithFlags(&eWr,   cudaEventDisableTiming);
        cudaEventCreateWithFlags(&eWk,   cudaEventDisableTiming);
        cudaEventCreateWithFlags(&eWv,   cudaEventDisableTiming);
        cudaEventCreateWithFlags(&eWo,   cudaEventDisableTiming);
        cudaEventCreateWithFlags(&eWrf,  cudaEventDisableTiming);
        cudaEventCreateWithFlags(&eWkf,  cudaEventDisableTiming);
        cudaEventCreateWithFlags(&eWvf,  cudaEventDisableTiming);
        cudaEventCreateWithFlags(&eGk,   cudaEventDisableTiming);
        cudaEventCreateWithFlags(&eGv,   cudaEventDisableTiming);
        cudaEventCreateWithFlags(&eGrr,  cudaEventDisableTiming);
        cudaEventCreateWithFlags(&eMix2, cudaEventDisableTiming);
        s_init = true;
    }

    const int ebH = (T_SEQ * H_DIM) / 256;
    const dim3 gHH(H_DIM / 128, T_SEQ / 128);   // (16, 32)
    const dim3 gHI(I_DIM / 128, T_SEQ / 128);   // (64, 32)
    const dim3 wtHH(H_DIM / 32, H_DIM / 32);
    const dim3 wtHI(I_DIM / 32, H_DIM / 32);
    const dim3 wtIH(H_DIM / 32, I_DIM / 32);

    // ---- fork: side stream does all weight converts, per-weight events ----
    cudaEventRecord(eFork, 0);
    cudaStreamWaitEvent(sW, eFork, 0);
    convert_wt<<<wtHH, 256, 0, sW>>>(Wr, Wrh, Wrl, H_DIM, H_DIM);      cudaEventRecord(eWr, sW);
    convert_wt<<<wtHH, 256, 0, sW>>>(Wk, Wkh, Wkl, H_DIM, H_DIM);      cudaEventRecord(eWk, sW);
    convert_wt<<<wtHH, 256, 0, sW>>>(Wv, Wvh, Wvl, H_DIM, H_DIM);      cudaEventRecord(eWv, sW);
    convert_wt<<<wtHH, 256, 0, sW>>>(Wo, Woh, Wol, H_DIM, H_DIM);      cudaEventRecord(eWo, sW);
    convert_wt<<<wtHH, 256, 0, sW>>>(Wr_ff, Wrfh, Wrfl, H_DIM, H_DIM); cudaEventRecord(eWrf, sW);
    convert_wt<<<wtHI, 256, 0, sW>>>(Wk_ff, Wkfh, Wkfl, H_DIM, I_DIM); cudaEventRecord(eWkf, sW);
    convert_wt<<<wtIH, 256, 0, sW>>>(Wv_ff, Wvfh, Wvfl, I_DIM, H_DIM); cudaEventRecord(eWvf, sW);

    // ---- time-mix ----
    ln_kernel<<<T_SEQ, 256>>>(hidden, ln1_scale, ln1_bias, x);
    mix3_kernel<<<ebH, 256>>>(x, tm_k, tm_v, tm_r, Ah, Al, Vh, Vl, Rh, Rl);
    cudaEventRecord(eMix, 0);

    // r/k/v GEMMs run concurrently on 3 streams
    cudaStreamWaitEvent(0, eWr, 0);
    mma_gemm<1><<<gHH, 256, SMEM_BYTES>>>(Rh, Rl, Wrh, Wrl, r, nullptr, nullptr, nullptr, T_SEQ, H_DIM, H_DIM);

    cudaStreamWaitEvent(s3, eMix, 0);
    cudaStreamWaitEvent(s3, eWk, 0);
    mma_gemm<0><<<gHH, 256, SMEM_BYTES, s3>>>(Ah, Al, Wkh, Wkl, k, nullptr, nullptr, nullptr, T_SEQ, H_DIM, H_DIM);
    cudaEventRecord(eGk, s3);

    cudaStreamWaitEvent(s4, eMix, 0);
    cudaStreamWaitEvent(s4, eWv, 0);
    mma_gemm<0><<<gHH, 256, SMEM_BYTES, s4>>>(Vh, Vl, Wvh, Wvl, v, nullptr, nullptr, nullptr, T_SEQ, H_DIM, H_DIM);
    cudaEventRecord(eGv, s4);

    cudaStreamWaitEvent(0, eGk, 0);
    cudaStreamWaitEvent(0, eGv, 0);
    wkv_kernel<<<H_DIM / 256, 256>>>(k, v, r, time_first, time_decay, Ah, Al);  // r*wkv -> Ah/Al

    cudaStreamWaitEvent(0, eWo, 0);
    mma_gemm<3><<<gHH, 256, SMEM_BYTES>>>(Ah, Al, Woh, Wol, out, hidden, nullptr, nullptr, T_SEQ, H_DIM, H_DIM);

    // ---- channel-mix ----
    ln_kernel<<<T_SEQ, 256>>>(out, ln2_scale, ln2_bias, x);
    mix2_kernel<<<ebH, 256>>>(x, ffn_tm_k, ffn_tm_r, Ah, Al, Rh, Rl);
    cudaEventRecord(eMix2, 0);

    // rr GEMM on s3 concurrent with the big Wk_ff GEMM on main
    cudaStreamWaitEvent(s3, eMix2, 0);
    cudaStreamWaitEvent(s3, eWrf, 0);
    mma_gemm<1><<<gHH, 256, SMEM_BYTES, s3>>>(Rh, Rl, Wrfh, Wrfl, r, nullptr, nullptr, nullptr, T_SEQ, H_DIM, H_DIM);
    cudaEventRecord(eGrr, s3);

    cudaStreamWaitEvent(0, eWkf, 0);
    mma_gemm<4><<<gHI, 256, SMEM_BYTES>>>(Ah, Al, Wkfh, Wkfl, nullptr, nullptr, Kh, Kl, T_SEQ, I_DIM, H_DIM);

    cudaStreamWaitEvent(0, eWvf, 0);
    mma_gemm<0><<<gHH, 256, SMEM_BYTES>>>(Kh, Kl, Wvfh, Wvfl, v, nullptr, nullptr, nullptr, T_SEQ, H_DIM, I_DIM);

    cudaStreamWaitEvent(0, eGrr, 0);
    gate_add_kernel<<<ebH, 256>>>(out, r, v);
}

// round 16
// speedup vs baseline: 1.2939x; 1.0057x over previous
#include <cuda_runtime.h>
#include <cuda_bf16.h>
#include <math_constants.h>
#include <cstdint>

#define T_SEQ 4096
#define H_DIM 2048
#define I_DIM 8192

// ---------------- scratch (device globals; no runtime allocation) ----------------
__device__ float g_k  [T_SEQ * H_DIM];
__device__ float g_v  [T_SEQ * H_DIM];       // v, later kv
__device__ float g_r  [T_SEQ * H_DIM];       // sigmoid(r), later rr
// bf16 split activation buffers
__device__ __nv_bfloat16 g_Ah[(size_t)T_SEQ * H_DIM];  // kx / wkv / ffn-kx
__device__ __nv_bfloat16 g_Al[(size_t)T_SEQ * H_DIM];
__device__ __nv_bfloat16 g_Vh[(size_t)T_SEQ * H_DIM];  // vx
__device__ __nv_bfloat16 g_Vl[(size_t)T_SEQ * H_DIM];
__device__ __nv_bfloat16 g_Rh[(size_t)T_SEQ * H_DIM];  // rx / ffn-rx
__device__ __nv_bfloat16 g_Rl[(size_t)T_SEQ * H_DIM];
__device__ __nv_bfloat16 g_Kh[(size_t)T_SEQ * I_DIM];  // kk split (ffn inner)
__device__ __nv_bfloat16 g_Kl[(size_t)T_SEQ * I_DIM];
// per-weight split buffers (transposed, K-major) — converts run on a side stream
__device__ __nv_bfloat16 g_Wr_h [(size_t)H_DIM * H_DIM];
__device__ __nv_bfloat16 g_Wr_l [(size_t)H_DIM * H_DIM];
__device__ __nv_bfloat16 g_Wk_h [(size_t)H_DIM * H_DIM];
__device__ __nv_bfloat16 g_Wk_l [(size_t)H_DIM * H_DIM];
__device__ __nv_bfloat16 g_Wv_h [(size_t)H_DIM * H_DIM];
__device__ __nv_bfloat16 g_Wv_l [(size_t)H_DIM * H_DIM];
__device__ __nv_bfloat16 g_Wo_h [(size_t)H_DIM * H_DIM];
__device__ __nv_bfloat16 g_Wo_l [(size_t)H_DIM * H_DIM];
__device__ __nv_bfloat16 g_Wrf_h[(size_t)H_DIM * H_DIM];
__device__ __nv_bfloat16 g_Wrf_l[(size_t)H_DIM * H_DIM];
__device__ __nv_bfloat16 g_Wkf_h[(size_t)H_DIM * I_DIM];
__device__ __nv_bfloat16 g_Wkf_l[(size_t)H_DIM * I_DIM];
__device__ __nv_bfloat16 g_Wvf_h[(size_t)H_DIM * I_DIM];
__device__ __nv_bfloat16 g_Wvf_l[(size_t)H_DIM * I_DIM];

// ---------------- helpers ----------------
__device__ __forceinline__ uint32_t smem_u32(const void* p) {
    uint32_t a;
    asm("{ .reg .u64 t; cvta.to.shared.u64 t, %1; cvt.u32.u64 %0, t; }" : "=r"(a) : "l"(p));
    return a;
}
#define SWZ128(o) ((o) ^ (((o) >> 3) & 0x70))

__device__ __forceinline__ void cp_async16(uint32_t dst, const void* src) {
    asm volatile("cp.async.cg.shared.global [%0], [%1], 16;" :: "r"(dst), "l"(src));
}
#define CP_COMMIT() asm volatile("cp.async.commit_group;" ::: "memory")

__device__ __forceinline__ void ldm_x4(uint32_t* r, uint32_t addr) {
    asm volatile("ldmatrix.sync.aligned.m8n8.x4.shared.b16 {%0,%1,%2,%3}, [%4];"
                 : "=r"(r[0]), "=r"(r[1]), "=r"(r[2]), "=r"(r[3]) : "r"(addr));
}
__device__ __forceinline__ void mma16816(float* c, const uint32_t* a, const uint32_t* b) {
    asm volatile(
        "mma.sync.aligned.m16n8k16.row.col.f32.bf16.bf16.f32 "
        "{%0,%1,%2,%3}, {%4,%5,%6,%7}, {%8,%9}, {%0,%1,%2,%3};"
        : "+f"(c[0]), "+f"(c[1]), "+f"(c[2]), "+f"(c[3])
        : "r"(a[0]), "r"(a[1]), "r"(a[2]), "r"(a[3]), "r"(b[0]), "r"(b[1]));
}
__device__ __forceinline__ void split_bf16(float v, __nv_bfloat16& h, __nv_bfloat16& l) {
    h = __float2bfloat16(v);
    l = __float2bfloat16(v - __bfloat162float(h));
}

// ---------------- mma.sync GEMM v3c (strided; unchanged inner loop) ----------------
// BM=128/BN=128/BK=32, packed hi|lo rows, 3 stages, 3 passes/chunk, launch_bounds(256,2).
// EPI: 0=none 1=sigmoid 2=relu^2(fp32) 3=+=res 4=relu^2 -> bf16 hi/lo split
#define STAGE_BYTES 32768
template <int EPI>
__global__ __launch_bounds__(256, 2) void mma_gemm(const __nv_bfloat16* __restrict__ Ah,
                                                   const __nv_bfloat16* __restrict__ Al,
                                                   const __nv_bfloat16* __restrict__ Bh,
                                                   const __nv_bfloat16* __restrict__ Bl,
                                                   float* __restrict__ C,
                                                   const float* __restrict__ res,
                                                   __nv_bfloat16* __restrict__ Chi,
                                                   __nv_bfloat16* __restrict__ Clo,
                                                   int M, int N, int K,
                                                   int lda, int ldb, int ldc) {
    extern __shared__ char dsm[];
    char* smem = (char*)(((uintptr_t)dsm + 1023u) & ~(uintptr_t)1023u);
    const uint32_t sbase = smem_u32(smem);

    const int tid = threadIdx.x;
    const int wid = tid >> 5, lane = tid & 31;
    const int warp_m = wid & 3;
    const int warp_n = wid >> 2;
    const int bm = blockIdx.y * 128, bn = blockIdx.x * 128;

    const int KC = K >> 5;

    const int a_row = (lane & 15);
    const int a_kb  = (lane >> 4) * 16;
    const int b_row = (lane & 7) + ((lane >> 4) << 3);
    const int b_kb  = ((lane >> 3) & 1) * 16;

    float acc[2][8][4];
#pragma unroll
    for (int i = 0; i < 2; i++)
#pragma unroll
        for (int j = 0; j < 8; j++)
#pragma unroll
            for (int q = 0; q < 4; q++) acc[i][j][q] = 0.f;

    auto issue = [&](int c, int p) {
        const int k0 = c << 5;
        const uint32_t st = sbase + p * STAGE_BYTES;
#pragma unroll
        for (int j = 0; j < 4; j++) {
            const int i = tid + 256 * j;
            const int row = i >> 3, seg = i & 7;
            const uint32_t off = SWZ128((uint32_t)(row * 128 + seg * 16));
            const int s4 = seg & 3;
            const __nv_bfloat16* As = (seg < 4) ? Ah : Al;
            const __nv_bfloat16* Bs = (seg < 4) ? Bh : Bl;
            cp_async16(st + off,          As + (size_t)(bm + row) * lda + k0 + s4 * 8);
            cp_async16(st + 16384 + off,  Bs + (size_t)(bn + row) * ldb + k0 + s4 * 8);
        }
        CP_COMMIT();
    };

    issue(0, 0);
    issue(1, 1);

    for (int c = 0; c < KC; c++) {
        if (c + 1 < KC) {
            asm volatile("cp.async.wait_group 1;" ::: "memory");
        } else {
            asm volatile("cp.async.wait_group 0;" ::: "memory");
        }
        __syncthreads();
        if (c + 2 < KC) issue(c + 2, (c + 2) % 3);

        const uint32_t st = sbase + (c % 3) * STAGE_BYTES;
#pragma unroll
        for (int pass = 0; pass < 3; pass++) {
            const uint32_t aofs = (pass == 1) ? 64u : 0u;
            const uint32_t bofs = (pass == 2) ? 64u : 0u;
#pragma unroll
            for (int ks = 0; ks < 2; ks++) {
                uint32_t afr[2][4];
#pragma unroll
                for (int mt = 0; mt < 2; mt++) {
                    const uint32_t off = (uint32_t)((warp_m * 32 + mt * 16 + a_row) * 128) + aofs + ks * 32 + a_kb;
                    ldm_x4(afr[mt], st + SWZ128(off));
                }
                uint32_t bfr[8][2];
#pragma unroll
                for (int np = 0; np < 4; np++) {
                    uint32_t r[4];
                    const uint32_t off = (uint32_t)((warp_n * 64 + np * 16 + b_row) * 128) + bofs + ks * 32 + b_kb;
                    ldm_x4(r, st + 16384u + SWZ128(off));
                    bfr[2 * np][0] = r[0];  bfr[2 * np][1] = r[1];
                    bfr[2 * np + 1][0] = r[2];  bfr[2 * np + 1][1] = r[3];
                }
#pragma unroll
                for (int mt = 0; mt < 2; mt++)
#pragma unroll
                    for (int nt = 0; nt < 8; nt++)
                        mma16816(acc[mt][nt], afr[mt], bfr[nt]);
            }
        }
        __syncthreads();
    }

    const int trow = lane >> 2;
    const int tcol = (lane & 3) * 2;
#pragma unroll
    for (int mt = 0; mt < 2; mt++) {
#pragma unroll
        for (int nt = 0; nt < 8; nt++) {
            const int row0 = bm + warp_m * 32 + mt * 16 + trow;
            const int col  = bn + warp_n * 64 + nt * 8 + tcol;
#pragma unroll
            for (int h = 0; h < 2; h++) {
                const int row = row0 + h * 8;
                float v0 = acc[mt][nt][2 * h + 0];
                float v1 = acc[mt][nt][2 * h + 1];
                const size_t base = (size_t)row * ldc + col;
                if (EPI == 1) {
                    v0 = 1.f / (1.f + __expf(-v0));
                    v1 = 1.f / (1.f + __expf(-v1));
                } else if (EPI == 2 || EPI == 4) {
                    v0 = fmaxf(v0, 0.f); v0 *= v0;
                    v1 = fmaxf(v1, 0.f); v1 *= v1;
                } else if (EPI == 3) {
                    const float2 rv = *reinterpret_cast<const float2*>(&res[base]);
                    v0 += rv.x; v1 += rv.y;
                }
                if (EPI == 4) {
                    __nv_bfloat16 h0, l0, h1, l1;
                    split_bf16(v0, h0, l0);
                    split_bf16(v1, h1, l1);
                    *reinterpret_cast<__nv_bfloat162*>(&Chi[base]) = __nv_bfloat162(h0, h1);
                    *reinterpret_cast<__nv_bfloat162*>(&Clo[base]) = __nv_bfloat162(l0, l1);
                } else {
                    *reinterpret_cast<float2*>(&C[base]) = make_float2(v0, v1);
                }
            }
        }
    }
}

// ---------------- weight transpose + split: W[K,N] fp32 -> [N,K] bf16 hi/lo ----------------
__global__ __launch_bounds__(256) void convert_wt(const float* __restrict__ W,
                                                  __nv_bfloat16* __restrict__ Th,
                                                  __nv_bfloat16* __restrict__ Tl,
                                                  int K, int N) {
    __shared__ float tile[32][33];
    const int tx = threadIdx.x & 31, ty = threadIdx.x >> 5;
    const int k0 = blockIdx.y * 32, n0 = blockIdx.x * 32;
#pragma unroll
    for (int j = 0; j < 4; j++)
        tile[ty + j * 8][tx] = W[(size_t)(k0 + ty + j * 8) * N + n0 + tx];
    __syncthreads();
#pragma unroll
    for (int j = 0; j < 4; j++) {
        const float v = tile[tx][ty + j * 8];
        __nv_bfloat16 h, l;
        split_bf16(v, h, l);
        const size_t o = (size_t)(n0 + ty + j * 8) * K + k0 + tx;
        Th[o] = h;
        Tl[o] = l;
    }
}

// ---------------- fused LayerNorm + token-shift mix ----------------
// Block t LNs rows t and t-1 (t=0: shift is exactly zero) and writes mixes directly.
template <bool THREE>
__global__ __launch_bounds__(256) void ln_mix_kernel(const float* __restrict__ in,
                                                     const float* __restrict__ sc,
                                                     const float* __restrict__ bi,
                                                     const float* __restrict__ tmk,
                                                     const float* __restrict__ tmv,
                                                     const float* __restrict__ tmr,
                                                     __nv_bfloat16* __restrict__ kxh, __nv_bfloat16* __restrict__ kxl,
                                                     __nv_bfloat16* __restrict__ vxh, __nv_bfloat16* __restrict__ vxl,
                                                     __nv_bfloat16* __restrict__ rxh, __nv_bfloat16* __restrict__ rxl) {
    __shared__ float red[4][8];
    const int t = blockIdx.x;
    const bool has_prev = (t > 0);
    const float* row0 = in + (size_t)t * H_DIM;
    const float* row1 = in + (size_t)(has_prev ? t - 1 : t) * H_DIM;
    float v0[8], v1[8];
    float s0 = 0.f, q0 = 0.f, s1 = 0.f, q1 = 0.f;
#pragma unroll
    for (int i = 0; i < 8; i++) {
        v0[i] = row0[threadIdx.x + i * 256];
        v1[i] = row1[threadIdx.x + i * 256];
        s0 += v0[i]; q0 += v0[i] * v0[i];
        s1 += v1[i]; q1 += v1[i] * v1[i];
    }
#pragma unroll
    for (int o = 16; o; o >>= 1) {
        s0 += __shfl_xor_sync(0xffffffffu, s0, o);
        q0 += __shfl_xor_sync(0xffffffffu, q0, o);
        s1 += __shfl_xor_sync(0xffffffffu, s1, o);
        q1 += __shfl_xor_sync(0xffffffffu, q1, o);
    }
    const int w = threadIdx.x >> 5, l = threadIdx.x & 31;
    if (l == 0) { red[0][w] = s0; red[1][w] = q0; red[2][w] = s1; red[3][w] = q1; }
    __syncthreads();
    if (threadIdx.x < 32) {
        s0 = (l < 8) ? red[0][l] : 0.f;
        q0 = (l < 8) ? red[1][l] : 0.f;
        s1 = (l < 8) ? red[2][l] : 0.f;
        q1 = (l < 8) ? red[3][l] : 0.f;
#pragma unroll
        for (int o = 4; o; o >>= 1) {
            s0 += __shfl_xor_sync(0xffffffffu, s0, o);
            q0 += __shfl_xor_sync(0xffffffffu, q0, o);
            s1 += __shfl_xor_sync(0xffffffffu, s1, o);
            q1 += __shfl_xor_sync(0xffffffffu, q1, o);
        }
        if (l == 0) { red[0][0] = s0; red[1][0] = q0; red[2][0] = s1; red[3][0] = q1; }
    }
    __syncthreads();
    const float m0 = red[0][0] * (1.f / H_DIM);
    const float i0 = rsqrtf(red[1][0] * (1.f / H_DIM) - m0 * m0 + 1e-5f);
    const float m1 = red[2][0] * (1.f / H_DIM);
    const float i1 = rsqrtf(red[3][0] * (1.f / H_DIM) - m1 * m1 + 1e-5f);
#pragma unroll
    for (int i = 0; i < 8; i++) {
        const int h = threadIdx.x + i * 256;
        const size_t idx = (size_t)t * H_DIM + h;
        const float xv = (v0[i] - m0) * i0 * sc[h] + bi[h];
        const float cx = has_prev ? ((v1[i] - m1) * i1 * sc[h] + bi[h]) : 0.f;
        const float a = tmk[h], c = tmr[h];
        __nv_bfloat16 hh, ll;
        split_bf16(xv * a + cx * (1.f - a), hh, ll);  kxh[idx] = hh; kxl[idx] = ll;
        split_bf16(xv * c + cx * (1.f - c), hh, ll);  rxh[idx] = hh; rxl[idx] = ll;
        if (THREE) {
            const float b = tmv[h];
            split_bf16(xv * b + cx * (1.f - b), hh, ll);  vxh[idx] = hh; vxl[idx] = ll;
        }
    }
}

// ---------------- WKV serial scan with group-of-16 register prefetch ----------------
#define WKV_G 16
__global__ __launch_bounds__(256) void wkv_kernel(const float* __restrict__ k,
                                                  const float* __restrict__ v,
                                                  const float* __restrict__ r,
                                                  const float* __restrict__ time_first,
                                                  const float* __restrict__ time_decay,
                                                  __nv_bfloat16* __restrict__ outh,
                                                  __nv_bfloat16* __restrict__ outl) {
    const int h = blockIdx.x * 256 + threadIdx.x;
    const float u = time_first[h];
    const float w = -__expf(time_decay[h]);
    float aa = 0.f, bb = 0.f, pp = -CUDART_INF_F;

    float kb[WKV_G], vb[WKV_G], rb[WKV_G];
    for (int t0 = 0; t0 < T_SEQ; t0 += WKV_G) {
        const size_t base0 = (size_t)t0 * H_DIM + h;
#pragma unroll
        for (int j = 0; j < WKV_G; j++) {
            const size_t idx = base0 + (size_t)j * H_DIM;
            kb[j] = __ldg(&k[idx]);
            vb[j] = __ldg(&v[idx]);
            rb[j] = __ldg(&r[idx]);
        }
#pragma unroll
        for (int j = 0; j < WKV_G; j++) {
            const float kk = kb[j];
            const float vv = vb[j];
            const float ww = u + kk;
            const float p  = fmaxf(pp, ww);
            const float e1 = __expf(pp - p);
            const float e2 = __expf(ww - p);
            const float o  = rb[j] * __fdividef(e1 * aa + e2 * vv, e1 * bb + e2);
            __nv_bfloat16 hh, ll;
            split_bf16(o, hh, ll);
            const size_t idx = base0 + (size_t)j * H_DIM;
            outh[idx] = hh; outl[idx] = ll;
            const float ww2 = w + pp;
            const float p2  = fmaxf(ww2, kk);
            const float e1b = __expf(ww2 - p2);
            const float e2b = __expf(kk - p2);
            aa = e1b * aa + e2b * vv;
            bb = e1b * bb + e2b;
            pp = p2;
        }
    }
}

__global__ __launch_bounds__(256) void gate_add_kernel(float* __restrict__ out,
                                                       const float* __restrict__ rr,
                                                       const float* __restrict__ kv) {
    const int idx = blockIdx.x * 256 + threadIdx.x;
    out[idx] += rr[idx] * kv[idx];
}

// ---------------- launch ----------------
extern "C" void kernel_launch(void* const* d_in, const int* in_sizes, int n_in,
                              void* d_out, int out_size) {
    const float* hidden     = (const float*)d_in[0];
    const float* ln1_scale  = (const float*)d_in[1];
    const float* ln1_bias   = (const float*)d_in[2];
    const float* ln2_scale  = (const float*)d_in[3];
    const float* ln2_bias   = (const float*)d_in[4];
    const float* time_decay = (const float*)d_in[5];
    const float* time_first = (const float*)d_in[6];
    const float* tm_k       = (const float*)d_in[7];
    const float* tm_v       = (const float*)d_in[8];
    const float* tm_r       = (const float*)d_in[9];
    const float* Wk         = (const float*)d_in[10];
    const float* Wv         = (const float*)d_in[11];
    const float* Wr         = (const float*)d_in[12];
    const float* Wo         = (const float*)d_in[13];
    const float* ffn_tm_k   = (const float*)d_in[14];
    const float* ffn_tm_r   = (const float*)d_in[15];
    const float* Wk_ff      = (const float*)d_in[16];
    const float* Wv_ff      = (const float*)d_in[17];
    const float* Wr_ff      = (const float*)d_in[18];
    float* out = (float*)d_out;

    float *k, *v, *r;
    __nv_bfloat16 *Ah, *Al, *Vh, *Vl, *Rh, *Rl, *Kh, *Kl;
    __nv_bfloat16 *Wrh, *Wrl, *Wkh, *Wkl, *Wvh, *Wvl, *Woh, *Wol, *Wrfh, *Wrfl, *Wkfh, *Wkfl, *Wvfh, *Wvfl;
    cudaGetSymbolAddress((void**)&k,  g_k);
    cudaGetSymbolAddress((void**)&v,  g_v);
    cudaGetSymbolAddress((void**)&r,  g_r);
    cudaGetSymbolAddress((void**)&Ah, g_Ah);
    cudaGetSymbolAddress((void**)&Al, g_Al);
    cudaGetSymbolAddress((void**)&Vh, g_Vh);
    cudaGetSymbolAddress((void**)&Vl, g_Vl);
    cudaGetSymbolAddress((void**)&Rh, g_Rh);
    cudaGetSymbolAddress((void**)&Rl, g_Rl);
    cudaGetSymbolAddress((void**)&Kh, g_Kh);
    cudaGetSymbolAddress((void**)&Kl, g_Kl);
    cudaGetSymbolAddress((void**)&Wrh,  g_Wr_h);   cudaGetSymbolAddress((void**)&Wrl,  g_Wr_l);
    cudaGetSymbolAddress((void**)&Wkh,  g_Wk_h);   cudaGetSymbolAddress((void**)&Wkl,  g_Wk_l);
    cudaGetSymbolAddress((void**)&Wvh,  g_Wv_h);   cudaGetSymbolAddress((void**)&Wvl,  g_Wv_l);
    cudaGetSymbolAddress((void**)&Woh,  g_Wo_h);   cudaGetSymbolAddress((void**)&Wol,  g_Wo_l);
    cudaGetSymbolAddress((void**)&Wrfh, g_Wrf_h);  cudaGetSymbolAddress((void**)&Wrfl, g_Wrf_l);
    cudaGetSymbolAddress((void**)&Wkfh, g_Wkf_h);  cudaGetSymbolAddress((void**)&Wkfl, g_Wkf_l);
    cudaGetSymbolAddress((void**)&Wvfh, g_Wvf_h);  cudaGetSymbolAddress((void**)&Wvfl, g_Wvf_l);

    static const int SMEM_BYTES = 3 * STAGE_BYTES + 1024;   // 99328 -> 2 CTAs/SM
    static bool s_init = false;
    static cudaStream_t sW, s3, s4;
    static cudaEvent_t eFork, eMix, eW3, eWAll, eGk, eGv, eGrr, eMix2, eKV;
    static cudaEvent_t eKK[2];
    if (!s_init) {
        cudaFuncSetAttribute(mma_gemm<0>, cudaFuncAttributeMaxDynamicSharedMemorySize, SMEM_BYTES);
        cudaFuncSetAttribute(mma_gemm<1>, cudaFuncAttributeMaxDynamicSharedMemorySize, SMEM_BYTES);
        cudaFuncSetAttribute(mma_gemm<3>, cudaFuncAttributeMaxDynamicSharedMemorySize, SMEM_BYTES);
        cudaFuncSetAttribute(mma_gemm<4>, cudaFuncAttributeMaxDynamicSharedMemorySize, SMEM_BYTES);
        cudaStreamCreateWithFlags(&sW, cudaStreamNonBlocking);
        cudaStreamCreateWithFlags(&s3, cudaStreamNonBlocking);
        cudaStreamCreateWithFlags(&s4, cudaStreamNonBlocking);
        cudaEventCreateWithFlags(&eFork, cudaEventDisableTiming);
        cudaEventCreateWithFlags(&eMix,  cudaEventDisableTiming);
        cudaEventCreateWithFlags(&eW3,   cudaEventDisableTiming);
        cudaEventCreateWithFlags(&eWAll, cudaEventDisableTiming);
        cudaEventCreateWithFlags(&eGk,   cudaEventDisableTiming);
        cudaEventCreateWithFlags(&eGv,   cudaEventDisableTiming);
        cudaEventCreateWithFlags(&eGrr,  cudaEventDisableTiming);
        cudaEventCreateWithFlags(&eMix2, cudaEventDisableTiming);
        cudaEventCreateWithFlags(&eKV,   cudaEventDisableTiming);
        cudaEventCreateWithFlags(&eKK[0], cudaEventDisableTiming);
        cudaEventCreateWithFlags(&eKK[1], cudaEventDisableTiming);
        s_init = true;
    }

    const int ebH = (T_SEQ * H_DIM) / 256;
    const dim3 gHH(H_DIM / 128, T_SEQ / 128);   // (16, 32)
    const dim3 gHS(I_DIM / 2 / 128, T_SEQ / 128); // N=4096 segment -> (32, 32)
    const dim3 wtHH(H_DIM / 32, H_DIM / 32);
    const dim3 wtHI(I_DIM / 32, H_DIM / 32);
    const dim3 wtIH(H_DIM / 32, I_DIM / 32);

    // ---- fork: side stream does all weight converts; two coverage events ----
    cudaEventRecord(eFork, 0);
    cudaStreamWaitEvent(sW, eFork, 0);
    convert_wt<<<wtHH, 256, 0, sW>>>(Wr, Wrh, Wrl, H_DIM, H_DIM);
    convert_wt<<<wtHH, 256, 0, sW>>>(Wk, Wkh, Wkl, H_DIM, H_DIM);
    convert_wt<<<wtHH, 256, 0, sW>>>(Wv, Wvh, Wvl, H_DIM, H_DIM);
    cudaEventRecord(eW3, sW);
    convert_wt<<<wtHH, 256, 0, sW>>>(Wo, Woh, Wol, H_DIM, H_DIM);
    convert_wt<<<wtHH, 256, 0, sW>>>(Wr_ff, Wrfh, Wrfl, H_DIM, H_DIM);
    convert_wt<<<wtHI, 256, 0, sW>>>(Wk_ff, Wkfh, Wkfl, H_DIM, I_DIM);
    convert_wt<<<wtIH, 256, 0, sW>>>(Wv_ff, Wvfh, Wvfl, I_DIM, H_DIM);
    cudaEventRecord(eWAll, sW);

    // ---- time-mix: fused LN1+mix3 ----
    ln_mix_kernel<true><<<T_SEQ, 256>>>(hidden, ln1_scale, ln1_bias, tm_k, tm_v, tm_r,
                                        Ah, Al, Vh, Vl, Rh, Rl);
    cudaEventRecord(eMix, 0);

    // r/k/v GEMMs concurrent on 3 streams
    cudaStreamWaitEvent(0, eW3, 0);
    mma_gemm<1><<<gHH, 256, SMEM_BYTES>>>(Rh, Rl, Wrh, Wrl, r, nullptr, nullptr, nullptr,
                                          T_SEQ, H_DIM, H_DIM, H_DIM, H_DIM, H_DIM);

    cudaStreamWaitEvent(s3, eMix, 0);
    cudaStreamWaitEvent(s3, eW3, 0);
    mma_gemm<0><<<gHH, 256, SMEM_BYTES, s3>>>(Ah, Al, Wkh, Wkl, k, nullptr, nullptr, nullptr,
                                              T_SEQ, H_DIM, H_DIM, H_DIM, H_DIM, H_DIM);
    cudaEventRecord(eGk, s3);

    cudaStreamWaitEvent(s4, eMix, 0);
    cudaStreamWaitEvent(s4, eW3, 0);
    mma_gemm<0><<<gHH, 256, SMEM_BYTES, s4>>>(Vh, Vl, Wvh, Wvl, v, nullptr, nullptr, nullptr,
                                              T_SEQ, H_DIM, H_DIM, H_DIM, H_DIM, H_DIM);
    cudaEventRecord(eGv, s4);

    cudaStreamWaitEvent(0, eGk, 0);
    cudaStreamWaitEvent(0, eGv, 0);
    wkv_kernel<<<H_DIM / 256, 256>>>(k, v, r, time_first, time_decay, Ah, Al);  // r*wkv -> Ah/Al

    cudaStreamWaitEvent(0, eWAll, 0);
    mma_gemm<3><<<gHH, 256, SMEM_BYTES>>>(Ah, Al, Woh, Wol, out, hidden, nullptr, nullptr,
                                          T_SEQ, H_DIM, H_DIM, H_DIM, H_DIM, H_DIM);

    // ---- channel-mix: fused LN2+mix2 ----
    ln_mix_kernel<false><<<T_SEQ, 256>>>(out, ln2_scale, ln2_bias, ffn_tm_k, nullptr, ffn_tm_r,
                                         Ah, Al, nullptr, nullptr, Rh, Rl);
    cudaEventRecord(eMix2, 0);

    // rr GEMM on s3 concurrent with the segmented FFN pipeline
    cudaStreamWaitEvent(s3, eMix2, 0);
    cudaStreamWaitEvent(s3, eWAll, 0);
    mma_gemm<1><<<gHH, 256, SMEM_BYTES, s3>>>(Rh, Rl, Wrfh, Wrfl, r, nullptr, nullptr, nullptr,
                                              T_SEQ, H_DIM, H_DIM, H_DIM, H_DIM, H_DIM);
    cudaEventRecord(eGrr, s3);

    // ---- 2-segment FFN pipeline: kk0 -> (kk1 || kv0) -> kv1 ----
    cudaStreamWaitEvent(s4, eWAll, 0);
    const int SEG = I_DIM / 2;  // 4096
    for (int i = 0; i < 2; i++) {
        mma_gemm<4><<<gHS, 256, SMEM_BYTES>>>(
            Ah, Al,
            Wkfh + (size_t)i * SEG * H_DIM, Wkfl + (size_t)i * SEG * H_DIM,
            nullptr, nullptr, Kh + (size_t)i * SEG, Kl + (size_t)i * SEG,
            T_SEQ, SEG, H_DIM, H_DIM, H_DIM, I_DIM);
        cudaEventRecord(eKK[i], 0);
        cudaStreamWaitEvent(s4, eKK[i], 0);
        if (i == 0) {
            mma_gemm<0><<<gHH, 256, SMEM_BYTES, s4>>>(
                Kh, Kl, Wvfh, Wvfl, v, nullptr, nullptr, nullptr,
                T_SEQ, H_DIM, SEG, I_DIM, I_DIM, H_DIM);
        } else {
            mma_gemm<3><<<gHH, 256, SMEM_BYTES, s4>>>(
                Kh + (size_t)i * SEG, Kl + (size_t)i * SEG,
                Wvfh + (size_t)i * SEG, Wvfl + (size_t)i * SEG,
                v, v, nullptr, nullptr,
                T_SEQ, H_DIM, SEG, I_DIM, I_DIM, H_DIM);
        }
    }
    cudaEventRecord(eKV, s4);

    cudaStreamWaitEvent(0, eKV, 0);
    cudaStreamWaitEvent(0, eGrr, 0);
    gate_add_kernel<<<ebH, 256>>>(out, r, v);
}

// round 17
// speedup vs baseline: 1.3099x; 1.0124x over previous
#include <cuda_runtime.h>
#include <cuda_bf16.h>
#include <math_constants.h>
#include <cstdint>

#define T_SEQ 4096
#define H_DIM 2048
#define I_DIM 8192

// ---------------- scratch (device globals; no runtime allocation) ----------------
__device__ float g_k  [T_SEQ * H_DIM];
__device__ float g_v  [T_SEQ * H_DIM];       // v, later kv
__device__ float g_r  [T_SEQ * H_DIM];       // sigmoid(r), later rr
// bf16 split activation buffers
__device__ __nv_bfloat16 g_Ah[(size_t)T_SEQ * H_DIM];  // kx / wkv / ffn-kx
__device__ __nv_bfloat16 g_Al[(size_t)T_SEQ * H_DIM];
__device__ __nv_bfloat16 g_Vh[(size_t)T_SEQ * H_DIM];  // vx
__device__ __nv_bfloat16 g_Vl[(size_t)T_SEQ * H_DIM];
__device__ __nv_bfloat16 g_Rh[(size_t)T_SEQ * H_DIM];  // rx / ffn-rx
__device__ __nv_bfloat16 g_Rl[(size_t)T_SEQ * H_DIM];
__device__ __nv_bfloat16 g_Kh[(size_t)T_SEQ * I_DIM];  // kk split (ffn inner)
__device__ __nv_bfloat16 g_Kl[(size_t)T_SEQ * I_DIM];
// per-weight split buffers (transposed, K-major)
__device__ __nv_bfloat16 g_Wr_h [(size_t)H_DIM * H_DIM];
__device__ __nv_bfloat16 g_Wr_l [(size_t)H_DIM * H_DIM];
__device__ __nv_bfloat16 g_Wk_h [(size_t)H_DIM * H_DIM];
__device__ __nv_bfloat16 g_Wk_l [(size_t)H_DIM * H_DIM];
__device__ __nv_bfloat16 g_Wv_h [(size_t)H_DIM * H_DIM];
__device__ __nv_bfloat16 g_Wv_l [(size_t)H_DIM * H_DIM];
__device__ __nv_bfloat16 g_Wo_h [(size_t)H_DIM * H_DIM];
__device__ __nv_bfloat16 g_Wo_l [(size_t)H_DIM * H_DIM];
__device__ __nv_bfloat16 g_Wrf_h[(size_t)H_DIM * H_DIM];
__device__ __nv_bfloat16 g_Wrf_l[(size_t)H_DIM * H_DIM];
__device__ __nv_bfloat16 g_Wkf_h[(size_t)H_DIM * I_DIM];
__device__ __nv_bfloat16 g_Wkf_l[(size_t)H_DIM * I_DIM];
__device__ __nv_bfloat16 g_Wvf_h[(size_t)H_DIM * I_DIM];
__device__ __nv_bfloat16 g_Wvf_l[(size_t)H_DIM * I_DIM];

// ---------------- helpers ----------------
__device__ __forceinline__ uint32_t smem_u32(const void* p) {
    uint32_t a;
    asm("{ .reg .u64 t; cvta.to.shared.u64 t, %1; cvt.u32.u64 %0, t; }" : "=r"(a) : "l"(p));
    return a;
}
#define SWZ128(o) ((o) ^ (((o) >> 3) & 0x70))

__device__ __forceinline__ void cp_async16(uint32_t dst, const void* src) {
    asm volatile("cp.async.cg.shared.global [%0], [%1], 16;" :: "r"(dst), "l"(src));
}
#define CP_COMMIT() asm volatile("cp.async.commit_group;" ::: "memory")

__device__ __forceinline__ void ldm_x4(uint32_t* r, uint32_t addr) {
    asm volatile("ldmatrix.sync.aligned.m8n8.x4.shared.b16 {%0,%1,%2,%3}, [%4];"
                 : "=r"(r[0]), "=r"(r[1]), "=r"(r[2]), "=r"(r[3]) : "r"(addr));
}
__device__ __forceinline__ void mma16816(float* c, const uint32_t* a, const uint32_t* b) {
    asm volatile(
        "mma.sync.aligned.m16n8k16.row.col.f32.bf16.bf16.f32 "
        "{%0,%1,%2,%3}, {%4,%5,%6,%7}, {%8,%9}, {%0,%1,%2,%3};"
        : "+f"(c[0]), "+f"(c[1]), "+f"(c[2]), "+f"(c[3])
        : "r"(a[0]), "r"(a[1]), "r"(a[2]), "r"(a[3]), "r"(b[0]), "r"(b[1]));
}
__device__ __forceinline__ void split_bf16(float v, __nv_bfloat16& h, __nv_bfloat16& l) {
    h = __float2bfloat16(v);
    l = __float2bfloat16(v - __bfloat162float(h));
}

#define STAGE_BYTES 32768

// ---------------- shared GEMM mainloop as a device function ----------------
// Computes the 128x128 (bm,bn) tile of A[M,K]@B[N,K]^T with the 3-term split.
// Leaves results in acc[2][8][4]. Caller does the epilogue.
__device__ __forceinline__ void gemm_core(const __nv_bfloat16* __restrict__ Ah,
                                          const __nv_bfloat16* __restrict__ Al,
                                          const __nv_bfloat16* __restrict__ Bh,
                                          const __nv_bfloat16* __restrict__ Bl,
                                          int K, int lda, int ldb,
                                          int bm, int bn, char* smem,
                                          float acc[2][8][4]) {
    const uint32_t sbase = smem_u32(smem);
    const int tid = threadIdx.x;
    const int wid = tid >> 5, lane = tid & 31;
    const int warp_m = wid & 3;
    const int warp_n = wid >> 2;
    const int KC = K >> 5;

    const int a_row = (lane & 15);
    const int a_kb  = (lane >> 4) * 16;
    const int b_row = (lane & 7) + ((lane >> 4) << 3);
    const int b_kb  = ((lane >> 3) & 1) * 16;

    auto issue = [&](int c, int p) {
        const int k0 = c << 5;
        const uint32_t st = sbase + p * STAGE_BYTES;
#pragma unroll
        for (int j = 0; j < 4; j++) {
            const int i = tid + 256 * j;
            const int row = i >> 3, seg = i & 7;
            const uint32_t off = SWZ128((uint32_t)(row * 128 + seg * 16));
            const int s4 = seg & 3;
            const __nv_bfloat16* As = (seg < 4) ? Ah : Al;
            const __nv_bfloat16* Bs = (seg < 4) ? Bh : Bl;
            cp_async16(st + off,          As + (size_t)(bm + row) * lda + k0 + s4 * 8);
            cp_async16(st + 16384 + off,  Bs + (size_t)(bn + row) * ldb + k0 + s4 * 8);
        }
        CP_COMMIT();
    };

    issue(0, 0);
    issue(1, 1);

    for (int c = 0; c < KC; c++) {
        if (c + 1 < KC) {
            asm volatile("cp.async.wait_group 1;" ::: "memory");
        } else {
            asm volatile("cp.async.wait_group 0;" ::: "memory");
        }
        __syncthreads();
        if (c + 2 < KC) issue(c + 2, (c + 2) % 3);

        const uint32_t st = sbase + (c % 3) * STAGE_BYTES;
#pragma unroll
        for (int pass = 0; pass < 3; pass++) {
            const uint32_t aofs = (pass == 1) ? 64u : 0u;
            const uint32_t bofs = (pass == 2) ? 64u : 0u;
#pragma unroll
            for (int ks = 0; ks < 2; ks++) {
                uint32_t afr[2][4];
#pragma unroll
                for (int mt = 0; mt < 2; mt++) {
                    const uint32_t off = (uint32_t)((warp_m * 32 + mt * 16 + a_row) * 128) + aofs + ks * 32 + a_kb;
                    ldm_x4(afr[mt], st + SWZ128(off));
                }
                uint32_t bfr[8][2];
#pragma unroll
                for (int np = 0; np < 4; np++) {
                    uint32_t rr[4];
                    const uint32_t off = (uint32_t)((warp_n * 64 + np * 16 + b_row) * 128) + bofs + ks * 32 + b_kb;
                    ldm_x4(rr, st + 16384u + SWZ128(off));
                    bfr[2 * np][0] = rr[0];  bfr[2 * np][1] = rr[1];
                    bfr[2 * np + 1][0] = rr[2];  bfr[2 * np + 1][1] = rr[3];
                }
#pragma unroll
                for (int mt = 0; mt < 2; mt++)
#pragma unroll
                    for (int nt = 0; nt < 8; nt++)
                        mma16816(acc[mt][nt], afr[mt], bfr[nt]);
            }
        }
        __syncthreads();
    }
}

// ---------------- generic strided GEMM (EPI-templated), as in R16 ----------------
// EPI: 0=none 1=sigmoid 3=+=res 4=relu^2 -> bf16 hi/lo split
template <int EPI>
__global__ __launch_bounds__(256, 2) void mma_gemm(const __nv_bfloat16* __restrict__ Ah,
                                                   const __nv_bfloat16* __restrict__ Al,
                                                   const __nv_bfloat16* __restrict__ Bh,
                                                   const __nv_bfloat16* __restrict__ Bl,
                                                   float* __restrict__ C,
                                                   const float* __restrict__ res,
                                                   __nv_bfloat16* __restrict__ Chi,
                                                   __nv_bfloat16* __restrict__ Clo,
                                                   int M, int N, int K,
                                                   int lda, int ldb, int ldc) {
    extern __shared__ char dsm[];
    char* smem = (char*)(((uintptr_t)dsm + 1023u) & ~(uintptr_t)1023u);
    const int bm = blockIdx.y * 128, bn = blockIdx.x * 128;

    float acc[2][8][4];
#pragma unroll
    for (int i = 0; i < 2; i++)
#pragma unroll
        for (int j = 0; j < 8; j++)
#pragma unroll
            for (int q = 0; q < 4; q++) acc[i][j][q] = 0.f;

    gemm_core(Ah, Al, Bh, Bl, K, lda, ldb, bm, bn, smem, acc);

    const int wid = threadIdx.x >> 5, lane = threadIdx.x & 31;
    const int warp_m = wid & 3, warp_n = wid >> 2;
    const int trow = lane >> 2;
    const int tcol = (lane & 3) * 2;
#pragma unroll
    for (int mt = 0; mt < 2; mt++) {
#pragma unroll
        for (int nt = 0; nt < 8; nt++) {
            const int row0 = bm + warp_m * 32 + mt * 16 + trow;
            const int col  = bn + warp_n * 64 + nt * 8 + tcol;
#pragma unroll
            for (int h = 0; h < 2; h++) {
                const int row = row0 + h * 8;
                float v0 = acc[mt][nt][2 * h + 0];
                float v1 = acc[mt][nt][2 * h + 1];
                const size_t base = (size_t)row * ldc + col;
                if (EPI == 1) {
                    v0 = 1.f / (1.f + __expf(-v0));
                    v1 = 1.f / (1.f + __expf(-v1));
                } else if (EPI == 4) {
                    v0 = fmaxf(v0, 0.f); v0 *= v0;
                    v1 = fmaxf(v1, 0.f); v1 *= v1;
                } else if (EPI == 3) {
                    const float2 rv = *reinterpret_cast<const float2*>(&res[base]);
                    v0 += rv.x; v1 += rv.y;
                }
                if (EPI == 4) {
                    __nv_bfloat16 h0, l0, h1, l1;
                    split_bf16(v0, h0, l0);
                    split_bf16(v1, h1, l1);
                    *reinterpret_cast<__nv_bfloat162*>(&Chi[base]) = __nv_bfloat162(h0, h1);
                    *reinterpret_cast<__nv_bfloat162*>(&Clo[base]) = __nv_bfloat162(l0, l1);
                } else {
                    *reinterpret_cast<float2*>(&C[base]) = make_float2(v0, v1);
                }
            }
        }
    }
}

// ---------------- batched QKV GEMM: blockIdx.z selects {r(sigmoid), k, v} ----------------
__global__ __launch_bounds__(256, 2) void qkv_gemm(const __nv_bfloat16* __restrict__ Rh, const __nv_bfloat16* __restrict__ Rl,
                                                   const __nv_bfloat16* __restrict__ Kxh, const __nv_bfloat16* __restrict__ Kxl,
                                                   const __nv_bfloat16* __restrict__ Vxh, const __nv_bfloat16* __restrict__ Vxl,
                                                   const __nv_bfloat16* __restrict__ Wrh, const __nv_bfloat16* __restrict__ Wrl,
                                                   const __nv_bfloat16* __restrict__ Wkh, const __nv_bfloat16* __restrict__ Wkl,
                                                   const __nv_bfloat16* __restrict__ Wvh, const __nv_bfloat16* __restrict__ Wvl,
                                                   float* __restrict__ r, float* __restrict__ k, float* __restrict__ v) {
    extern __shared__ char dsm[];
    char* smem = (char*)(((uintptr_t)dsm + 1023u) & ~(uintptr_t)1023u);
    const int z = blockIdx.z;
    const int bm = blockIdx.y * 128, bn = blockIdx.x * 128;

    const __nv_bfloat16 *Ah, *Al, *Bh, *Bl;
    float* C;
    if (z == 0)      { Ah = Rh;  Al = Rl;  Bh = Wrh; Bl = Wrl; C = r; }
    else if (z == 1) { Ah = Kxh; Al = Kxl; Bh = Wkh; Bl = Wkl; C = k; }
    else             { Ah = Vxh; Al = Vxl; Bh = Wvh; Bl = Wvl; C = v; }

    float acc[2][8][4];
#pragma unroll
    for (int i = 0; i < 2; i++)
#pragma unroll
        for (int j = 0; j < 8; j++)
#pragma unroll
            for (int q = 0; q < 4; q++) acc[i][j][q] = 0.f;

    gemm_core(Ah, Al, Bh, Bl, H_DIM, H_DIM, H_DIM, bm, bn, smem, acc);

    const int wid = threadIdx.x >> 5, lane = threadIdx.x & 31;
    const int warp_m = wid & 3, warp_n = wid >> 2;
    const int trow = lane >> 2;
    const int tcol = (lane & 3) * 2;
    const bool sig = (z == 0);
#pragma unroll
    for (int mt = 0; mt < 2; mt++) {
#pragma unroll
        for (int nt = 0; nt < 8; nt++) {
            const int row0 = bm + warp_m * 32 + mt * 16 + trow;
            const int col  = bn + warp_n * 64 + nt * 8 + tcol;
#pragma unroll
            for (int h = 0; h < 2; h++) {
                const int row = row0 + h * 8;
                float v0 = acc[mt][nt][2 * h + 0];
                float v1 = acc[mt][nt][2 * h + 1];
                if (sig) {
                    v0 = 1.f / (1.f + __expf(-v0));
                    v1 = 1.f / (1.f + __expf(-v1));
                }
                *reinterpret_cast<float2*>(&C[(size_t)row * H_DIM + col]) = make_float2(v0, v1);
            }
        }
    }
}

// ---------------- weight transpose + split: W[K,N] fp32 -> [N,K] bf16 hi/lo ----------------
__global__ __launch_bounds__(256) void convert_wt(const float* __restrict__ W,
                                                  __nv_bfloat16* __restrict__ Th,
                                                  __nv_bfloat16* __restrict__ Tl,
                                                  int K, int N) {
    __shared__ float tile[32][33];
    const int tx = threadIdx.x & 31, ty = threadIdx.x >> 5;
    const int k0 = blockIdx.y * 32, n0 = blockIdx.x * 32;
#pragma unroll
    for (int j = 0; j < 4; j++)
        tile[ty + j * 8][tx] = W[(size_t)(k0 + ty + j * 8) * N + n0 + tx];
    __syncthreads();
#pragma unroll
    for (int j = 0; j < 4; j++) {
        const float v = tile[tx][ty + j * 8];
        __nv_bfloat16 h, l;
        split_bf16(v, h, l);
        const size_t o = (size_t)(n0 + ty + j * 8) * K + k0 + tx;
        Th[o] = h;
        Tl[o] = l;
    }
}

// ---------------- fused LayerNorm + token-shift mix ----------------
template <bool THREE>
__global__ __launch_bounds__(256) void ln_mix_kernel(const float* __restrict__ in,
                                                     const float* __restrict__ sc,
                                                     const float* __restrict__ bi,
                                                     const float* __restrict__ tmk,
                                                     const float* __restrict__ tmv,
                                                     const float* __restrict__ tmr,
                                                     __nv_bfloat16* __restrict__ kxh, __nv_bfloat16* __restrict__ kxl,
                                                     __nv_bfloat16* __restrict__ vxh, __nv_bfloat16* __restrict__ vxl,
                                                     __nv_bfloat16* __restrict__ rxh, __nv_bfloat16* __restrict__ rxl) {
    __shared__ float red[4][8];
    const int t = blockIdx.x;
    const bool has_prev = (t > 0);
    const float* row0 = in + (size_t)t * H_DIM;
    const float* row1 = in + (size_t)(has_prev ? t - 1 : t) * H_DIM;
    float v0[8], v1[8];
    float s0 = 0.f, q0 = 0.f, s1 = 0.f, q1 = 0.f;
#pragma unroll
    for (int i = 0; i < 8; i++) {
        v0[i] = row0[threadIdx.x + i * 256];
        v1[i] = row1[threadIdx.x + i * 256];
        s0 += v0[i]; q0 += v0[i] * v0[i];
        s1 += v1[i]; q1 += v1[i] * v1[i];
    }
#pragma unroll
    for (int o = 16; o; o >>= 1) {
        s0 += __shfl_xor_sync(0xffffffffu, s0, o);
        q0 += __shfl_xor_sync(0xffffffffu, q0, o);
        s1 += __shfl_xor_sync(0xffffffffu, s1, o);
        q1 += __shfl_xor_sync(0xffffffffu, q1, o);
    }
    const int w = threadIdx.x >> 5, l = threadIdx.x & 31;
    if (l == 0) { red[0][w] = s0; red[1][w] = q0; red[2][w] = s1; red[3][w] = q1; }
    __syncthreads();
    if (threadIdx.x < 32) {
        s0 = (l < 8) ? red[0][l] : 0.f;
        q0 = (l < 8) ? red[1][l] : 0.f;
        s1 = (l < 8) ? red[2][l] : 0.f;
        q1 = (l < 8) ? red[3][l] : 0.f;
#pragma unroll
        for (int o = 4; o; o >>= 1) {
            s0 += __shfl_xor_sync(0xffffffffu, s0, o);
            q0 += __shfl_xor_sync(0xffffffffu, q0, o);
            s1 += __shfl_xor_sync(0xffffffffu, s1, o);
            q1 += __shfl_xor_sync(0xffffffffu, q1, o);
        }
        if (l == 0) { red[0][0] = s0; red[1][0] = q0; red[2][0] = s1; red[3][0] = q1; }
    }
    __syncthreads();
    const float m0 = red[0][0] * (1.f / H_DIM);
    const float i0 = rsqrtf(red[1][0] * (1.f / H_DIM) - m0 * m0 + 1e-5f);
    const float m1 = red[2][0] * (1.f / H_DIM);
    const float i1 = rsqrtf(red[3][0] * (1.f / H_DIM) - m1 * m1 + 1e-5f);
#pragma unroll
    for (int i = 0; i < 8; i++) {
        const int h = threadIdx.x + i * 256;
        const size_t idx = (size_t)t * H_DIM + h;
        const float xv = (v0[i] - m0) * i0 * sc[h] + bi[h];
        const float cx = has_prev ? ((v1[i] - m1) * i1 * sc[h] + bi[h]) : 0.f;
        const float a = tmk[h], c = tmr[h];
        __nv_bfloat16 hh, ll;
        split_bf16(xv * a + cx * (1.f - a), hh, ll);  kxh[idx] = hh; kxl[idx] = ll;
        split_bf16(xv * c + cx * (1.f - c), hh, ll);  rxh[idx] = hh; rxl[idx] = ll;
        if (THREE) {
            const float b = tmv[h];
            split_bf16(xv * b + cx * (1.f - b), hh, ll);  vxh[idx] = hh; vxl[idx] = ll;
        }
    }
}

// ---------------- WKV serial scan with group-of-32 register prefetch ----------------
#define WKV_G 32
__global__ __launch_bounds__(256) void wkv_kernel(const float* __restrict__ k,
                                                  const float* __restrict__ v,
                                                  const float* __restrict__ r,
                                                  const float* __restrict__ time_first,
                                                  const float* __restrict__ time_decay,
                                                  __nv_bfloat16* __restrict__ outh,
                                                  __nv_bfloat16* __restrict__ outl) {
    const int h = blockIdx.x * 256 + threadIdx.x;
    const float u = time_first[h];
    const float w = -__expf(time_decay[h]);
    float aa = 0.f, bb = 0.f, pp = -CUDART_INF_F;

    float kb[WKV_G], vb[WKV_G], rb[WKV_G];
    for (int t0 = 0; t0 < T_SEQ; t0 += WKV_G) {
        const size_t base0 = (size_t)t0 * H_DIM + h;
#pragma unroll
        for (int j = 0; j < WKV_G; j++) {
            const size_t idx = base0 + (size_t)j * H_DIM;
            kb[j] = __ldg(&k[idx]);
            vb[j] = __ldg(&v[idx]);
            rb[j] = __ldg(&r[idx]);
        }
#pragma unroll
        for (int j = 0; j < WKV_G; j++) {
            const float kk = kb[j];
            const float vv = vb[j];
            const float ww = u + kk;
            const float p  = fmaxf(pp, ww);
            const float e1 = __expf(pp - p);
            const float e2 = __expf(ww - p);
            const float o  = rb[j] * __fdividef(e1 * aa + e2 * vv, e1 * bb + e2);
            __nv_bfloat16 hh, ll;
            split_bf16(o, hh, ll);
            const size_t idx = base0 + (size_t)j * H_DIM;
            outh[idx] = hh; outl[idx] = ll;
            const float ww2 = w + pp;
            const float p2  = fmaxf(ww2, kk);
            const float e1b = __expf(ww2 - p2);
            const float e2b = __expf(kk - p2);
            aa = e1b * aa + e2b * vv;
            bb = e1b * bb + e2b;
            pp = p2;
        }
    }
}

__global__ __launch_bounds__(256) void gate_add_kernel(float* __restrict__ out,
                                                       const float* __restrict__ rr,
                                                       const float* __restrict__ kv) {
    const int idx = blockIdx.x * 256 + threadIdx.x;
    out[idx] += rr[idx] * kv[idx];
}

// ---------------- launch ----------------
extern "C" void kernel_launch(void* const* d_in, const int* in_sizes, int n_in,
                              void* d_out, int out_size) {
    const float* hidden     = (const float*)d_in[0];
    const float* ln1_scale  = (const float*)d_in[1];
    const float* ln1_bias   = (const float*)d_in[2];
    const float* ln2_scale  = (const float*)d_in[3];
    const float* ln2_bias   = (const float*)d_in[4];
    const float* time_decay = (const float*)d_in[5];
    const float* time_first = (const float*)d_in[6];
    const float* tm_k       = (const float*)d_in[7];
    const float* tm_v       = (const float*)d_in[8];
    const float* tm_r       = (const float*)d_in[9];
    const float* Wk         = (const float*)d_in[10];
    const float* Wv         = (const float*)d_in[11];
    const float* Wr         = (const float*)d_in[12];
    const float* Wo         = (const float*)d_in[13];
    const float* ffn_tm_k   = (const float*)d_in[14];
    const float* ffn_tm_r   = (const float*)d_in[15];
    const float* Wk_ff      = (const float*)d_in[16];
    const float* Wv_ff      = (const float*)d_in[17];
    const float* Wr_ff      = (const float*)d_in[18];
    float* out = (float*)d_out;

    float *k, *v, *r;
    __nv_bfloat16 *Ah, *Al, *Vh, *Vl, *Rh, *Rl, *Kh, *Kl;
    __nv_bfloat16 *Wrh, *Wrl, *Wkh, *Wkl, *Wvh, *Wvl, *Woh, *Wol, *Wrfh, *Wrfl, *Wkfh, *Wkfl, *Wvfh, *Wvfl;
    cudaGetSymbolAddress((void**)&k,  g_k);
    cudaGetSymbolAddress((void**)&v,  g_v);
    cudaGetSymbolAddress((void**)&r,  g_r);
    cudaGetSymbolAddress((void**)&Ah, g_Ah);
    cudaGetSymbolAddress((void**)&Al, g_Al);
    cudaGetSymbolAddress((void**)&Vh, g_Vh);
    cudaGetSymbolAddress((void**)&Vl, g_Vl);
    cudaGetSymbolAddress((void**)&Rh, g_Rh);
    cudaGetSymbolAddress((void**)&Rl, g_Rl);
    cudaGetSymbolAddress((void**)&Kh, g_Kh);
    cudaGetSymbolAddress((void**)&Kl, g_Kl);
    cudaGetSymbolAddress((void**)&Wrh,  g_Wr_h);   cudaGetSymbolAddress((void**)&Wrl,  g_Wr_l);
    cudaGetSymbolAddress((void**)&Wkh,  g_Wk_h);   cudaGetSymbolAddress((void**)&Wkl,  g_Wk_l);
    cudaGetSymbolAddress((void**)&Wvh,  g_Wv_h);   cudaGetSymbolAddress((void**)&Wvl,  g_Wv_l);
    cudaGetSymbolAddress((void**)&Woh,  g_Wo_h);   cudaGetSymbolAddress((void**)&Wol,  g_Wo_l);
    cudaGetSymbolAddress((void**)&Wrfh, g_Wrf_h);  cudaGetSymbolAddress((void**)&Wrfl, g_Wrf_l);
    cudaGetSymbolAddress((void**)&Wkfh, g_Wkf_h);  cudaGetSymbolAddress((void**)&Wkfl, g_Wkf_l);
    cudaGetSymbolAddress((void**)&Wvfh, g_Wvf_h);  cudaGetSymbolAddress((void**)&Wvfl, g_Wvf_l);

    static const int SMEM_BYTES = 3 * STAGE_BYTES + 1024;   // 99328 -> 2 CTAs/SM
    static bool s_init = false;
    static cudaStream_t sW, s3, s4;
    static cudaEvent_t eFork, eW3, eWAll, eGrr, eMix2, eKV;
    static cudaEvent_t eKK[2];
    if (!s_init) {
        cudaFuncSetAttribute(mma_gemm<0>, cudaFuncAttributeMaxDynamicSharedMemorySize, SMEM_BYTES);
        cudaFuncSetAttribute(mma_gemm<1>, cudaFuncAttributeMaxDynamicSharedMemorySize, SMEM_BYTES);
        cudaFuncSetAttribute(mma_gemm<3>, cudaFuncAttributeMaxDynamicSharedMemorySize, SMEM_BYTES);
        cudaFuncSetAttribute(mma_gemm<4>, cudaFuncAttributeMaxDynamicSharedMemorySize, SMEM_BYTES);
        cudaFuncSetAttribute(qkv_gemm,   cudaFuncAttributeMaxDynamicSharedMemorySize, SMEM_BYTES);
        cudaStreamCreateWithFlags(&sW, cudaStreamNonBlocking);
        cudaStreamCreateWithFlags(&s3, cudaStreamNonBlocking);
        cudaStreamCreateWithFlags(&s4, cudaStreamNonBlocking);
        cudaEventCreateWithFlags(&eFork, cudaEventDisableTiming);
        cudaEventCreateWithFlags(&eW3,   cudaEventDisableTiming);
        cudaEventCreateWithFlags(&eWAll, cudaEventDisableTiming);
        cudaEventCreateWithFlags(&eGrr,  cudaEventDisableTiming);
        cudaEventCreateWithFlags(&eMix2, cudaEventDisableTiming);
        cudaEventCreateWithFlags(&eKV,   cudaEventDisableTiming);
        cudaEventCreateWithFlags(&eKK[0], cudaEventDisableTiming);
        cudaEventCreateWithFlags(&eKK[1], cudaEventDisableTiming);
        s_init = true;
    }

    const int ebH = (T_SEQ * H_DIM) / 256;
    const dim3 gHH(H_DIM / 128, T_SEQ / 128);       // (16, 32)
    const dim3 gQKV(H_DIM / 128, T_SEQ / 128, 3);   // batched QKV
    const dim3 gHS(I_DIM / 2 / 128, T_SEQ / 128);   // N=4096 segment -> (32, 32)
    const dim3 wtHH(H_DIM / 32, H_DIM / 32);
    const dim3 wtHI(I_DIM / 32, H_DIM / 32);
    const dim3 wtIH(H_DIM / 32, I_DIM / 32);

    // ---- fork: side stream does all weight converts; two coverage events ----
    cudaEventRecord(eFork, 0);
    cudaStreamWaitEvent(sW, eFork, 0);
    convert_wt<<<wtHH, 256, 0, sW>>>(Wr, Wrh, Wrl, H_DIM, H_DIM);
    convert_wt<<<wtHH, 256, 0, sW>>>(Wk, Wkh, Wkl, H_DIM, H_DIM);
    convert_wt<<<wtHH, 256, 0, sW>>>(Wv, Wvh, Wvl, H_DIM, H_DIM);
    cudaEventRecord(eW3, sW);
    convert_wt<<<wtHH, 256, 0, sW>>>(Wo, Woh, Wol, H_DIM, H_DIM);
    convert_wt<<<wtHH, 256, 0, sW>>>(Wr_ff, Wrfh, Wrfl, H_DIM, H_DIM);
    convert_wt<<<wtHI, 256, 0, sW>>>(Wk_ff, Wkfh, Wkfl, H_DIM, I_DIM);
    convert_wt<<<wtIH, 256, 0, sW>>>(Wv_ff, Wvfh, Wvfl, I_DIM, H_DIM);
    cudaEventRecord(eWAll, sW);

    // ---- time-mix: fused LN1+mix3, then one batched QKV GEMM ----
    ln_mix_kernel<true><<<T_SEQ, 256>>>(hidden, ln1_scale, ln1_bias, tm_k, tm_v, tm_r,
                                        Ah, Al, Vh, Vl, Rh, Rl);

    cudaStreamWaitEvent(0, eW3, 0);
    qkv_gemm<<<gQKV, 256, SMEM_BYTES>>>(Rh, Rl, Ah, Al, Vh, Vl,
                                        Wrh, Wrl, Wkh, Wkl, Wvh, Wvl, r, k, v);

    wkv_kernel<<<H_DIM / 256, 256>>>(k, v, r, time_first, time_decay, Ah, Al);  // r*wkv -> Ah/Al

    cudaStreamWaitEvent(0, eWAll, 0);
    mma_gemm<3><<<gHH, 256, SMEM_BYTES>>>(Ah, Al, Woh, Wol, out, hidden, nullptr, nullptr,
                                          T_SEQ, H_DIM, H_DIM, H_DIM, H_DIM, H_DIM);

    // ---- channel-mix: fused LN2+mix2 ----
    ln_mix_kernel<false><<<T_SEQ, 256>>>(out, ln2_scale, ln2_bias, ffn_tm_k, nullptr, ffn_tm_r,
                                         Ah, Al, nullptr, nullptr, Rh, Rl);
    cudaEventRecord(eMix2, 0);

    // rr GEMM on s3 concurrent with the segmented FFN pipeline
    cudaStreamWaitEvent(s3, eMix2, 0);
    cudaStreamWaitEvent(s3, eWAll, 0);
    mma_gemm<1><<<gHH, 256, SMEM_BYTES, s3>>>(Rh, Rl, Wrfh, Wrfl, r, nullptr, nullptr, nullptr,
                                              T_SEQ, H_DIM, H_DIM, H_DIM, H_DIM, H_DIM);
    cudaEventRecord(eGrr, s3);

    // ---- 2-segment FFN pipeline: kk0 -> (kk1 || kv0) -> kv1 ----
    cudaStreamWaitEvent(s4, eWAll, 0);
    const int SEG = I_DIM / 2;  // 4096
    for (int i = 0; i < 2; i++) {
        mma_gemm<4><<<gHS, 256, SMEM_BYTES>>>(
            Ah, Al,
            Wkfh + (size_t)i * SEG * H_DIM, Wkfl + (size_t)i * SEG * H_DIM,
            nullptr, nullptr, Kh + (size_t)i * SEG, Kl + (size_t)i * SEG,
            T_SEQ, SEG, H_DIM, H_DIM, H_DIM, I_DIM);
        cudaEventRecord(eKK[i], 0);
        cudaStreamWaitEvent(s4, eKK[i], 0);
        if (i == 0) {
            mma_gemm<0><<<gHH, 256, SMEM_BYTES, s4>>>(
                Kh, Kl, Wvfh, Wvfl, v, nullptr, nullptr, nullptr,
                T_SEQ, H_DIM, SEG, I_DIM, I_DIM, H_DIM);
        } else {
            mma_gemm<3><<<gHH, 256, SMEM_BYTES, s4>>>(
                Kh + (size_t)i * SEG, Kl + (size_t)i * SEG,
                Wvfh + (size_t)i * SEG, Wvfl + (size_t)i * SEG,
                v, v, nullptr, nullptr,
                T_SEQ, H_DIM, SEG, I_DIM, I_DIM, H_DIM);
        }
    }
    cudaEventRecord(eKV, s4);

    cudaStreamWaitEvent(0, eKV, 0);
    cudaStreamWaitEvent(0, eGrr, 0);
    gate_add_kernel<<<ebH, 256>>>(out, r, v);
}